// round 4
// baseline (speedup 1.0000x reference)
#include <cuda_runtime.h>
#include <cuda_bf16.h>
#include <math.h>
#include <stdint.h>

#define BATCH   8
#define SEQ     200
#define NNODES  512
#define HID     64
#define NEDGES  2048
#define ALPHA   0.2f
#define NEGBIG  -9.0e15f

// ---------------- scratch (device globals, no allocation) ----------------
__device__ float g_h0[BATCH * NNODES * HID];
__device__ float g_Wh[BATCH * NNODES * HID];
__device__ float g_h1[BATCH * NNODES * HID];
__device__ float g_h2[BATCH * NNODES * HID];
__device__ float g_f1[BATCH * NNODES];
__device__ float g_f2[BATCH * NNODES];

// ---------------- bf16 helpers ----------------
__device__ __forceinline__ uint32_t pack_bf16(float lo, float hi) {
    uint32_t r;
    asm("{ .reg .b16 a, b;\n"
        "  cvt.rn.bf16.f32 a, %1;\n"
        "  cvt.rn.bf16.f32 b, %2;\n"
        "  mov.b32 %0, {a, b}; }"
        : "=r"(r) : "f"(lo), "f"(hi));
    return r;
}
__device__ __forceinline__ void mma_bf16(float* c,
                                         uint32_t a0, uint32_t a1, uint32_t a2, uint32_t a3,
                                         uint32_t b0, uint32_t b1) {
    asm volatile(
        "mma.sync.aligned.m16n8k16.row.col.f32.bf16.bf16.f32 "
        "{%0,%1,%2,%3}, {%4,%5,%6,%7}, {%8,%9}, {%0,%1,%2,%3};"
        : "+f"(c[0]), "+f"(c[1]), "+f"(c[2]), "+f"(c[3])
        : "r"(a0), "r"(a1), "r"(a2), "r"(a3), "r"(b0), "r"(b1));
}

// ---------------- Stage A: conv1+relu, conv2 as bf16 implicit GEMM --------
// One block per (b,n), 256 threads = 8 warps.
// GEMM: M = 200 (13 m16 tiles), N = 64 (8 n8 tiles), K = 160 = 80 K-pairs
//       (10 k16 chunks, chunk kc uses pairs 8kc..8kc+7).
// Pair p < 64 : (ic = p>>1, k = (p&1)*2, k+1)   -> A from pairA[ic] shifted array
// Pair p >= 64: (r = 10m+4, 10m+9), m = p-64    -> A from pairB[m]  ic-interleaved
// A value for pair p at row s = one aligned u32 (bf16x2) load.
#define PRW  264                          // pair-row width in u32 words
#define WP   72                           // wpair row stride (conflict-free)
#define S_PAIR_OFF 0                      // 48 rows x 264 = 12672 words
#define S_WP_OFF   12672                  // 80 x 72 = 5760
#define S_IN_OFF   (S_WP_OFF + 5760)      // 416
#define S_W1_OFF   (S_IN_OFF + 416)       // 320
#define S_RED_OFF  (S_W1_OFF + 320)       // 512
#define CONV_SMEM_FLOATS (S_RED_OFF + 512)
#define CONV_SMEM_BYTES  (CONV_SMEM_FLOATS * 4)

__global__ void __launch_bounds__(256, 2)
conv_fused_kernel(const float* __restrict__ x,
                  const float* __restrict__ w1, const float* __restrict__ b1,
                  const float* __restrict__ w2, const float* __restrict__ b2,
                  float* __restrict__ h0)
{
    extern __shared__ float sm[];
    uint32_t* s_pair = (uint32_t*)(sm + S_PAIR_OFF);
    uint32_t* s_wp   = (uint32_t*)(sm + S_WP_OFF);
    float*    s_in   = sm + S_IN_OFF;
    float*    s_w1   = sm + S_W1_OFF;
    float*    s_red  = sm + S_RED_OFF;

    const int bn  = blockIdx.x;
    const int b   = bn >> 9;
    const int n   = bn & 511;
    const int tid = threadIdx.x;

    // zero pair buffer (covers all im2col/tail padding) + input pad
    for (int i = tid; i < 48 * PRW; i += 256) s_pair[i] = 0u;
    for (int i = tid; i < 2 * 208; i += 256)  s_in[i] = 0.f;

    // conv1 weights
    for (int i = tid; i < 320; i += 256) s_w1[i] = w1[i];

    // conv2 weights -> pair-indexed bf16x2, [80][72]
    for (int i = tid; i < 80 * 64; i += 256) {
        int p = i >> 6, nn = i & 63;
        int re, ro;
        if (p < 64) { int ic = p >> 1; re = ic * 5 + ((p & 1) << 1); ro = re + 1; }
        else        { int m = p - 64;  re = 10 * m + 4;              ro = 10 * m + 9; }
        s_wp[p * WP + nn] = pack_bf16(w2[nn * 160 + re], w2[nn * 160 + ro]);
    }
    __syncthreads();

    // input: xf[bn][c][s] = x[b, s, 2n+c]
    const float* xb = x + (size_t)b * SEQ * (NNODES * 2) + 2 * n;
    for (int i = tid; i < 2 * SEQ; i += 256) {
        int s = i >> 1, c = i & 1;
        s_in[c * 208 + 2 + s] = xb[(size_t)s * (NNODES * 2) + c];
    }
    __syncthreads();

    // conv1 + relu -> scatter bf16 into pair arrays
    {
        __nv_bfloat16* pb16 = (__nv_bfloat16*)s_pair;
        for (int i = tid; i < 32 * SEQ; i += 256) {
            int oc = i / SEQ, s = i - oc * SEQ;
            const float* w  = s_w1 + oc * 10;
            const float* i0 = s_in + s;
            const float* i1 = s_in + 208 + s;
            float acc = b1[oc];
#pragma unroll
            for (int k = 0; k < 5; k++)
                acc = fmaf(w[k], i0[k], fmaf(w[5 + k], i1[k], acc));
            __nv_bfloat16 v = __float2bfloat16(fmaxf(acc, 0.f));
            int t  = s + 2;                      // h1 row position (pad 2)
            int wA = oc * PRW + t;
            pb16[2 * wA]           = v;          // pairA[ic][t].lo
            pb16[2 * (wA - 1) + 1] = v;          // pairA[ic][t-1].hi
            int mrow = 32 + (oc >> 1);
            pb16[2 * (mrow * PRW + t) + (oc & 1)] = v;   // pairB[m][t].{lo,hi}
        }
    }
    __syncthreads();

    // -------- bf16 tensor-core GEMM --------
    const int warp = tid >> 5;
    const int lane = tid & 31;
    const int g    = lane >> 2;
    const int t4   = lane & 3;

    float c[2][8][4];
#pragma unroll
    for (int mt = 0; mt < 2; mt++)
#pragma unroll
        for (int nt = 0; nt < 8; nt++)
#pragma unroll
            for (int q = 0; q < 4; q++) c[mt][nt][q] = 0.f;

#pragma unroll
    for (int kc = 0; kc < 10; kc++) {
        const int p0 = kc * 8 + t4;
        const int p1 = p0 + 4;
        const int ao0 = (p0 < 64) ? ((p0 >> 1) * PRW + ((p0 & 1) << 1))
                                  : ((p0 - 32) * PRW + 4);
        const int ao1 = (p1 < 64) ? ((p1 >> 1) * PRW + ((p1 & 1) << 1))
                                  : ((p1 - 32) * PRW + 4);

        uint32_t bb0[8], bb1[8];
#pragma unroll
        for (int nt = 0; nt < 8; nt++) {
            bb0[nt] = s_wp[p0 * WP + nt * 8 + g];
            bb1[nt] = s_wp[p1 * WP + nt * 8 + g];
        }
#pragma unroll
        for (int mt = 0; mt < 2; mt++) {
            const int tile = warp + 8 * mt;
            if (tile >= 13) continue;            // rows >= 208 are all padding
            const int sb = tile * 16 + g;
            uint32_t a0 = s_pair[ao0 + sb];
            uint32_t a1 = s_pair[ao0 + sb + 8];
            uint32_t a2 = s_pair[ao1 + sb];
            uint32_t a3 = s_pair[ao1 + sb + 8];
#pragma unroll
            for (int nt = 0; nt < 8; nt++)
                mma_bf16(c[mt][nt], a0, a1, a2, a3, bb0[nt], bb1[nt]);
        }
    }

    // -------- epilogue: bias + relu + masked sum over positions --------
#pragma unroll
    for (int nt = 0; nt < 8; nt++) {
        const int n0 = nt * 8 + 2 * t4;
        const float bias0 = b2[n0], bias1 = b2[n0 + 1];
        float s0 = 0.f, s1 = 0.f;
#pragma unroll
        for (int mt = 0; mt < 2; mt++) {
            const int tile = warp + 8 * mt;
            if (tile >= 13) continue;
            const int rA = tile * 16 + g;
            const int rB = rA + 8;
            if (rA < 200) {
                s0 += fmaxf(c[mt][nt][0] + bias0, 0.f);
                s1 += fmaxf(c[mt][nt][1] + bias1, 0.f);
            }
            if (rB < 200) {
                s0 += fmaxf(c[mt][nt][2] + bias0, 0.f);
                s1 += fmaxf(c[mt][nt][3] + bias1, 0.f);
            }
        }
#pragma unroll
        for (int off = 16; off >= 4; off >>= 1) {
            s0 += __shfl_down_sync(0xffffffffu, s0, off);
            s1 += __shfl_down_sync(0xffffffffu, s1, off);
        }
        if (lane < 4) {
            s_red[warp * 64 + nt * 8 + 2 * lane]     = s0;
            s_red[warp * 64 + nt * 8 + 2 * lane + 1] = s1;
        }
    }
    __syncthreads();

    if (tid < 64) {
        float t = 0.f;
#pragma unroll
        for (int w = 0; w < 8; w++) t += s_red[w * 64 + tid];
        h0[(size_t)bn * HID + tid] = t * (1.f / 200.f);
    }
}

// ---------------- Stage B: Wh = h @ W ; f1 = Wh@a[:64] ; f2 = Wh@a[64:] ----
__global__ void __launch_bounds__(256)
gat_pre_kernel(const float* __restrict__ h, const float* __restrict__ W,
               const float* __restrict__ a,
               float* __restrict__ Wh, float* __restrict__ f1, float* __restrict__ f2)
{
    __shared__ float sW[64 * 64];
    __shared__ float sh[16 * 64];
    __shared__ float s1[8][4], s2[8][4];

    const int tid  = threadIdx.x;
    const int row0 = blockIdx.x * 16;

    for (int i = tid; i < 64 * 64; i += 256) sW[i] = W[i];
    for (int i = tid; i < 16 * 64; i += 256) sh[i] = h[(size_t)row0 * 64 + i];
    __syncthreads();

    const int rg = tid >> 6;
    const int d  = tid & 63;
    float acc[4] = {0.f, 0.f, 0.f, 0.f};
#pragma unroll 8
    for (int k = 0; k < 64; k++) {
        float w = sW[k * 64 + d];
#pragma unroll
        for (int j = 0; j < 4; j++)
            acc[j] = fmaf(sh[(rg * 4 + j) * 64 + k], w, acc[j]);
    }
    const float a1v = a[d], a2v = a[64 + d];
    float v1[4], v2[4];
#pragma unroll
    for (int j = 0; j < 4; j++) {
        Wh[(size_t)(row0 + rg * 4 + j) * 64 + d] = acc[j];
        v1[j] = acc[j] * a1v;
        v2[j] = acc[j] * a2v;
    }
#pragma unroll
    for (int o = 16; o; o >>= 1)
#pragma unroll
        for (int j = 0; j < 4; j++) {
            v1[j] += __shfl_down_sync(0xffffffffu, v1[j], o);
            v2[j] += __shfl_down_sync(0xffffffffu, v2[j], o);
        }
    const int w = tid >> 5;
    if ((tid & 31) == 0)
#pragma unroll
        for (int j = 0; j < 4; j++) { s1[w][j] = v1[j]; s2[w][j] = v2[j]; }
    __syncthreads();
    if (tid < 16) {
        int gq = tid >> 2, j = tid & 3;
        f1[row0 + gq * 4 + j] = s1[2 * gq][j] + s1[2 * gq + 1][j];
        f2[row0 + gq * 4 + j] = s2[2 * gq][j] + s2[2 * gq + 1][j];
    }
}

// ---------------- Stage C: attention, 8 rows per block, j-tiled Wh ----------
__global__ void __launch_bounds__(256)
gat_att_kernel(const float* __restrict__ Wh, const float* __restrict__ f1,
               const float* __restrict__ f2, const int* __restrict__ adj,
               float* __restrict__ out, int do_relu)
{
    __shared__ float sp[8][512];
    __shared__ float sWh[64][65];
    __shared__ float ssum[8];

    const int blk = blockIdx.x;
    const int b   = blk >> 6;
    const int i0  = (blk & 63) * 8;
    const int tid = threadIdx.x;
    const int w   = tid >> 5;
    const int ln  = tid & 31;

    {
        const int i  = i0 + w;
        const int bi = b * NNODES + i;
        const float f1i = f1[bi];
        const float* f2b = f2 + b * NNODES;
        const int* adjrow = adj + (size_t)i * NNODES;

        float ev[16];
        float lmax = -3.4e38f;
#pragma unroll
        for (int t = 0; t < 16; t++) {
            int j = ln + t * 32;
            float e = f1i + f2b[j];
            e = (e > 0.f) ? e : ALPHA * e;
            e = (adjrow[j] > 0) ? e : NEGBIG;
            ev[t] = e;
            lmax = fmaxf(lmax, e);
        }
#pragma unroll
        for (int o = 16; o; o >>= 1)
            lmax = fmaxf(lmax, __shfl_xor_sync(0xffffffffu, lmax, o));
        float lsum = 0.f;
#pragma unroll
        for (int t = 0; t < 16; t++) {
            float p = expf(ev[t] - lmax);
            sp[w][ln + t * 32] = p;
            lsum += p;
        }
#pragma unroll
        for (int o = 16; o; o >>= 1)
            lsum += __shfl_xor_sync(0xffffffffu, lsum, o);
        if (ln == 0) ssum[w] = lsum;
    }
    __syncthreads();

    const int g = tid >> 6;
    const int d = tid & 63;
    const float* Whb = Wh + (size_t)b * NNODES * HID;
    float acc0 = 0.f, acc1 = 0.f;

    for (int jt = 0; jt < 8; jt++) {
#pragma unroll
        for (int t = 0; t < 16; t++) {
            int idx = tid + t * 256;
            int j = idx >> 6, dd = idx & 63;
            sWh[j][dd] = Whb[(size_t)(jt * 64 + j) * 64 + dd];
        }
        __syncthreads();
        const float* p0 = &sp[2 * g][jt * 64];
        const float* p1 = &sp[2 * g + 1][jt * 64];
#pragma unroll 8
        for (int j = 0; j < 64; j++) {
            float wv = sWh[j][d];
            acc0 = fmaf(p0[j], wv, acc0);
            acc1 = fmaf(p1[j], wv, acc1);
        }
        __syncthreads();
    }

    {
        float v0 = acc0 / ssum[2 * g];
        float v1 = acc1 / ssum[2 * g + 1];
        if (do_relu) { v0 = fmaxf(v0, 0.f); v1 = fmaxf(v1, 0.f); }
        out[(size_t)(b * NNODES + i0 + 2 * g) * HID + d]     = v0;
        out[(size_t)(b * NNODES + i0 + 2 * g + 1) * HID + d] = v1;
    }
}

// ---------------- Stage D: edge gather + MLP + sigmoid ----------------
__global__ void __launch_bounds__(64)
edge_mlp_kernel(const float* __restrict__ h, const int* __restrict__ eidx,
                const float* __restrict__ fc1w, const float* __restrict__ fc1b,
                const float* __restrict__ fc2w, const float* __restrict__ fc2b,
                float* __restrict__ out)
{
    __shared__ float she[128];
    __shared__ float sr[2];

    const int e   = blockIdx.x;
    const int b   = blockIdx.y;
    const int tid = threadIdx.x;

    const int i1 = eidx[2 * e];
    const int i2 = eidx[2 * e + 1];
    she[tid]      = h[((size_t)b * NNODES + i1) * HID + tid];
    she[64 + tid] = h[((size_t)b * NNODES + i2) * HID + tid];
    __syncthreads();

    float acc = fc1b[tid];
#pragma unroll 8
    for (int k = 0; k < 128; k++)
        acc = fmaf(she[k], fc1w[(size_t)k * 64 + tid], acc);
    acc = fmaxf(acc, 0.f);

    float v = acc * fc2w[tid];
#pragma unroll
    for (int o = 16; o; o >>= 1)
        v += __shfl_down_sync(0xffffffffu, v, o);
    if ((tid & 31) == 0) sr[tid >> 5] = v;
    __syncthreads();
    if (tid == 0) {
        float z = sr[0] + sr[1] + fc2b[0];
        out[(size_t)b * NEDGES + e] = 1.f / (1.f + expf(-z));
    }
}

// ---------------- launch ----------------
extern "C" void kernel_launch(void* const* d_in, const int* in_sizes, int n_in,
                              void* d_out, int out_size)
{
    const float* x    = (const float*)d_in[0];
    const int*   adj  = (const int*)  d_in[1];
    const int*   eidx = (const int*)  d_in[2];
    const float* w1   = (const float*)d_in[3];
    const float* b1   = (const float*)d_in[4];
    const float* w2   = (const float*)d_in[5];
    const float* b2   = (const float*)d_in[6];
    const float* W1   = (const float*)d_in[7];
    const float* a1   = (const float*)d_in[8];
    const float* W2   = (const float*)d_in[9];
    const float* a2   = (const float*)d_in[10];
    const float* fc1w = (const float*)d_in[11];
    const float* fc1b = (const float*)d_in[12];
    const float* fc2w = (const float*)d_in[13];
    const float* fc2b = (const float*)d_in[14];
    float* out = (float*)d_out;

    float *h0, *Wh, *h1, *h2, *f1, *f2;
    cudaGetSymbolAddress((void**)&h0, g_h0);
    cudaGetSymbolAddress((void**)&Wh, g_Wh);
    cudaGetSymbolAddress((void**)&h1, g_h1);
    cudaGetSymbolAddress((void**)&h2, g_h2);
    cudaGetSymbolAddress((void**)&f1, g_f1);
    cudaGetSymbolAddress((void**)&f2, g_f2);

    cudaFuncSetAttribute(conv_fused_kernel,
                         cudaFuncAttributeMaxDynamicSharedMemorySize,
                         CONV_SMEM_BYTES);

    // Stage A: conv feature extractor (bf16 tensor-core implicit GEMM)
    conv_fused_kernel<<<BATCH * NNODES, 256, CONV_SMEM_BYTES>>>(x, w1, b1, w2, b2, h0);

    // GAT layer 1 (relu on output)
    gat_pre_kernel<<<(BATCH * NNODES) / 16, 256>>>(h0, W1, a1, Wh, f1, f2);
    gat_att_kernel<<<(BATCH * NNODES) / 8, 256>>>(Wh, f1, f2, adj, h1, 1);

    // GAT layer 2 (no relu)
    gat_pre_kernel<<<(BATCH * NNODES) / 16, 256>>>(h1, W2, a2, Wh, f1, f2);
    gat_att_kernel<<<(BATCH * NNODES) / 8, 256>>>(Wh, f1, f2, adj, h2, 0);

    // Edge MLP
    dim3 eg(NEDGES, BATCH);
    edge_mlp_kernel<<<eg, 64>>>(h2, eidx, fc1w, fc1b, fc2w, fc2b, out);
}

// round 5
// speedup vs baseline: 1.0409x; 1.0409x over previous
#include <cuda_runtime.h>
#include <cuda_bf16.h>
#include <math.h>
#include <stdint.h>

#define BATCH   8
#define SEQ     200
#define NNODES  512
#define HID     64
#define NEDGES  2048
#define ALPHA   0.2f
#define NEGBIG  -9.0e15f

// ---------------- scratch (device globals, no allocation) ----------------
__device__ float g_h0[BATCH * NNODES * HID];
__device__ float g_Wh[BATCH * NNODES * HID];
__device__ float g_h1[BATCH * NNODES * HID];
__device__ float g_h2[BATCH * NNODES * HID];
__device__ float g_f1[BATCH * NNODES];
__device__ float g_f2[BATCH * NNODES];

// ---------------- bf16 helpers ----------------
__device__ __forceinline__ uint32_t pack_bf16(float lo, float hi) {
    uint32_t r;
    asm("{ .reg .b16 a, b;\n"
        "  cvt.rn.bf16.f32 a, %1;\n"
        "  cvt.rn.bf16.f32 b, %2;\n"
        "  mov.b32 %0, {a, b}; }"
        : "=r"(r) : "f"(lo), "f"(hi));
    return r;
}
__device__ __forceinline__ void mma_bf16(float* c,
                                         uint32_t a0, uint32_t a1, uint32_t a2, uint32_t a3,
                                         uint32_t b0, uint32_t b1) {
    asm volatile(
        "mma.sync.aligned.m16n8k16.row.col.f32.bf16.bf16.f32 "
        "{%0,%1,%2,%3}, {%4,%5,%6,%7}, {%8,%9}, {%0,%1,%2,%3};"
        : "+f"(c[0]), "+f"(c[1]), "+f"(c[2]), "+f"(c[3])
        : "r"(a0), "r"(a1), "r"(a2), "r"(a3), "r"(b0), "r"(b1));
}

// ---------------- Stage A: conv1+relu, conv2 as bf16 implicit GEMM --------
// One block per (b,n), 256 threads = 8 warps.
// conv2 treated as width-6 kernel with zero 6th tap:
//   K-pair p = ic*3 + jj (jj in 0..2), pairs = 96, k16 chunks = 12.
//   A word for pair p at out-row s = pairA[ic][s + 2*jj], pairA[ic][t] =
//   (h[t], h[t+1]) bf16x2, h = padded conv1 output (h[t]=conv1[t-2], t in [2,202)).
//   B word for pair p, channel n = (w2[n][ic*5+2jj], jj<2 ? w2[n][ic*5+2jj+1] : 0).
// M = 200 (13 m16 tiles, warps cover tile = warp and warp+8 if <13).
#define PRW  216                          // pairA row width (u32 words)
#define WP   72                           // B pair row stride (conflict-free)
#define S_PAIR_OFF 0                      // 32*216 = 6912 words
#define S_WP_OFF   6912                   // 96*72  = 6912 words
#define S_IN_OFF   (S_WP_OFF + 6912)      // 416
#define S_W1_OFF   (S_IN_OFF + 416)       // 320
#define S_RED_OFF  (S_W1_OFF + 320)       // 512
#define CONV_SMEM_FLOATS (S_RED_OFF + 512)    // 15072
#define CONV_SMEM_BYTES  (CONV_SMEM_FLOATS * 4)

__global__ void __launch_bounds__(256, 2)
conv_fused_kernel(const float* __restrict__ x,
                  const float* __restrict__ w1, const float* __restrict__ b1,
                  const float* __restrict__ w2, const float* __restrict__ b2,
                  float* __restrict__ h0)
{
    extern __shared__ float sm[];
    uint32_t* s_pair = (uint32_t*)(sm + S_PAIR_OFF);
    uint32_t* s_wp   = (uint32_t*)(sm + S_WP_OFF);
    float*    s_in   = sm + S_IN_OFF;
    float*    s_w1   = sm + S_W1_OFF;
    float*    s_red  = sm + S_RED_OFF;

    const int bn  = blockIdx.x;
    const int b   = bn >> 9;
    const int n   = bn & 511;
    const int tid = threadIdx.x;

    for (int i = tid; i < 2 * 208; i += 256) s_in[i] = 0.f;
    for (int i = tid; i < 320; i += 256) s_w1[i] = w1[i];

    // conv2 weights -> pair-indexed bf16x2, [96][72]
    for (int i = tid; i < 96 * 64; i += 256) {
        int p = i >> 6, nn = i & 63;
        int ic = p / 3, jj = p - ic * 3;
        const float* wrow = w2 + nn * 160 + ic * 5 + 2 * jj;
        float lo = wrow[0];
        float hi = (jj < 2) ? wrow[1] : 0.f;
        s_wp[p * WP + nn] = pack_bf16(lo, hi);
    }
    __syncthreads();

    // input: xf[bn][c][s] = x[b, s, 2n+c]  (padded by 2 on each side)
    const float* xb = x + (size_t)b * SEQ * (NNODES * 2) + 2 * n;
    for (int i = tid; i < 2 * SEQ; i += 256) {
        int s = i >> 1, c = i & 1;
        s_in[c * 208 + 2 + s] = xb[(size_t)s * (NNODES * 2) + c];
    }
    __syncthreads();

    // conv1 + relu -> pair words directly (uniform 28 values / 27 words per thread)
    {
        const int ic = tid >> 3;
        const int j  = tid & 7;
        const int t0 = 27 * j;
        const float b1i = b1[ic];
        const float* w  = s_w1 + ic * 10;

        float hv[28];
#pragma unroll
        for (int q = 0; q < 28; q++) {
            int t = t0 + q;              // padded coord
            float acc = 0.f;
            if (t >= 2 && t < 202) {
                int s = t - 2;
                const float* i0 = s_in + s;
                const float* i1 = s_in + 208 + s;
                float a = b1i;
#pragma unroll
                for (int k = 0; k < 5; k++)
                    a = fmaf(w[k], i0[k], fmaf(w[5 + k], i1[k], a));
                acc = fmaxf(a, 0.f);
            }
            hv[q] = acc;
        }
        uint32_t* prow = s_pair + ic * PRW + t0;
#pragma unroll
        for (int q = 0; q < 27; q++)
            prow[q] = pack_bf16(hv[q], hv[q + 1]);
    }
    __syncthreads();

    // -------- bf16 tensor-core GEMM --------
    const int warp = tid >> 5;
    const int lane = tid & 31;
    const int g    = lane >> 2;
    const int t4   = lane & 3;

    float c[2][8][4];
#pragma unroll
    for (int mt = 0; mt < 2; mt++)
#pragma unroll
        for (int nt = 0; nt < 8; nt++)
#pragma unroll
            for (int q = 0; q < 4; q++) c[mt][nt][q] = 0.f;

    for (int kc = 0; kc < 12; kc++) {
        const int p0 = kc * 8 + t4;
        const int p1 = p0 + 4;
        const int ic0 = p0 / 3, jj0 = p0 - ic0 * 3;
        const int ic1 = p1 / 3, jj1 = p1 - ic1 * 3;
        const int ao0 = ic0 * PRW + 2 * jj0;
        const int ao1 = ic1 * PRW + 2 * jj1;

        uint32_t bb0[8], bb1[8];
#pragma unroll
        for (int nt = 0; nt < 8; nt++) {
            bb0[nt] = s_wp[p0 * WP + nt * 8 + g];
            bb1[nt] = s_wp[p1 * WP + nt * 8 + g];
        }
#pragma unroll
        for (int mt = 0; mt < 2; mt++) {
            const int tile = warp + 8 * mt;
            if (tile >= 13) continue;
            const int sb = tile * 16 + g;
            uint32_t a0 = s_pair[ao0 + sb];
            uint32_t a1 = s_pair[ao0 + sb + 8];
            uint32_t a2 = s_pair[ao1 + sb];
            uint32_t a3 = s_pair[ao1 + sb + 8];
#pragma unroll
            for (int nt = 0; nt < 8; nt++)
                mma_bf16(c[mt][nt], a0, a1, a2, a3, bb0[nt], bb1[nt]);
        }
    }

    // -------- epilogue: bias + relu + masked sum over positions --------
#pragma unroll
    for (int nt = 0; nt < 8; nt++) {
        const int n0 = nt * 8 + 2 * t4;
        const float bias0 = b2[n0], bias1 = b2[n0 + 1];
        float s0 = 0.f, s1 = 0.f;
#pragma unroll
        for (int mt = 0; mt < 2; mt++) {
            const int tile = warp + 8 * mt;
            if (tile >= 13) continue;
            const int rA = tile * 16 + g;
            const int rB = rA + 8;
            if (rA < 200) {
                s0 += fmaxf(c[mt][nt][0] + bias0, 0.f);
                s1 += fmaxf(c[mt][nt][1] + bias1, 0.f);
            }
            if (rB < 200) {
                s0 += fmaxf(c[mt][nt][2] + bias0, 0.f);
                s1 += fmaxf(c[mt][nt][3] + bias1, 0.f);
            }
        }
#pragma unroll
        for (int off = 16; off >= 4; off >>= 1) {
            s0 += __shfl_down_sync(0xffffffffu, s0, off);
            s1 += __shfl_down_sync(0xffffffffu, s1, off);
        }
        if (lane < 4) {
            s_red[warp * 64 + nt * 8 + 2 * lane]     = s0;
            s_red[warp * 64 + nt * 8 + 2 * lane + 1] = s1;
        }
    }
    __syncthreads();

    if (tid < 64) {
        float t = 0.f;
#pragma unroll
        for (int w = 0; w < 8; w++) t += s_red[w * 64 + tid];
        h0[(size_t)bn * HID + tid] = t * (1.f / 200.f);
    }
}

// ---------------- Stage B: Wh = h @ W ; f1 = Wh@a[:64] ; f2 = Wh@a[64:] ----
__global__ void __launch_bounds__(256)
gat_pre_kernel(const float* __restrict__ h, const float* __restrict__ W,
               const float* __restrict__ a,
               float* __restrict__ Wh, float* __restrict__ f1, float* __restrict__ f2)
{
    __shared__ float sW[64 * 64];
    __shared__ float sh[16 * 64];
    __shared__ float s1[8][4], s2[8][4];

    const int tid  = threadIdx.x;
    const int row0 = blockIdx.x * 16;

    for (int i = tid; i < 64 * 64; i += 256) sW[i] = W[i];
    for (int i = tid; i < 16 * 64; i += 256) sh[i] = h[(size_t)row0 * 64 + i];
    __syncthreads();

    const int rg = tid >> 6;
    const int d  = tid & 63;
    float acc[4] = {0.f, 0.f, 0.f, 0.f};
#pragma unroll 8
    for (int k = 0; k < 64; k++) {
        float w = sW[k * 64 + d];
#pragma unroll
        for (int j = 0; j < 4; j++)
            acc[j] = fmaf(sh[(rg * 4 + j) * 64 + k], w, acc[j]);
    }
    const float a1v = a[d], a2v = a[64 + d];
    float v1[4], v2[4];
#pragma unroll
    for (int j = 0; j < 4; j++) {
        Wh[(size_t)(row0 + rg * 4 + j) * 64 + d] = acc[j];
        v1[j] = acc[j] * a1v;
        v2[j] = acc[j] * a2v;
    }
#pragma unroll
    for (int o = 16; o; o >>= 1)
#pragma unroll
        for (int j = 0; j < 4; j++) {
            v1[j] += __shfl_down_sync(0xffffffffu, v1[j], o);
            v2[j] += __shfl_down_sync(0xffffffffu, v2[j], o);
        }
    const int w = tid >> 5;
    if ((tid & 31) == 0)
#pragma unroll
        for (int j = 0; j < 4; j++) { s1[w][j] = v1[j]; s2[w][j] = v2[j]; }
    __syncthreads();
    if (tid < 16) {
        int gq = tid >> 2, j = tid & 3;
        f1[row0 + gq * 4 + j] = s1[2 * gq][j] + s1[2 * gq + 1][j];
        f2[row0 + gq * 4 + j] = s2[2 * gq][j] + s2[2 * gq + 1][j];
    }
}

// ---------------- Stage C: attention, 8 rows per block, j-tiled Wh ----------
__global__ void __launch_bounds__(256)
gat_att_kernel(const float* __restrict__ Wh, const float* __restrict__ f1,
               const float* __restrict__ f2, const int* __restrict__ adj,
               float* __restrict__ out, int do_relu)
{
    __shared__ float sp[8][512];
    __shared__ float sWh[64][65];
    __shared__ float ssum[8];

    const int blk = blockIdx.x;
    const int b   = blk >> 6;
    const int i0  = (blk & 63) * 8;
    const int tid = threadIdx.x;
    const int w   = tid >> 5;
    const int ln  = tid & 31;

    {
        const int i  = i0 + w;
        const int bi = b * NNODES + i;
        const float f1i = f1[bi];
        const float* f2b = f2 + b * NNODES;
        const int* adjrow = adj + (size_t)i * NNODES;

        float ev[16];
        float lmax = -3.4e38f;
#pragma unroll
        for (int t = 0; t < 16; t++) {
            int j = ln + t * 32;
            float e = f1i + f2b[j];
            e = (e > 0.f) ? e : ALPHA * e;
            e = (adjrow[j] > 0) ? e : NEGBIG;
            ev[t] = e;
            lmax = fmaxf(lmax, e);
        }
#pragma unroll
        for (int o = 16; o; o >>= 1)
            lmax = fmaxf(lmax, __shfl_xor_sync(0xffffffffu, lmax, o));
        float lsum = 0.f;
#pragma unroll
        for (int t = 0; t < 16; t++) {
            float p = expf(ev[t] - lmax);
            sp[w][ln + t * 32] = p;
            lsum += p;
        }
#pragma unroll
        for (int o = 16; o; o >>= 1)
            lsum += __shfl_xor_sync(0xffffffffu, lsum, o);
        if (ln == 0) ssum[w] = lsum;
    }
    __syncthreads();

    const int g = tid >> 6;
    const int d = tid & 63;
    const float* Whb = Wh + (size_t)b * NNODES * HID;
    float acc0 = 0.f, acc1 = 0.f;

    for (int jt = 0; jt < 8; jt++) {
#pragma unroll
        for (int t = 0; t < 16; t++) {
            int idx = tid + t * 256;
            int j = idx >> 6, dd = idx & 63;
            sWh[j][dd] = Whb[(size_t)(jt * 64 + j) * 64 + dd];
        }
        __syncthreads();
        const float* p0 = &sp[2 * g][jt * 64];
        const float* p1 = &sp[2 * g + 1][jt * 64];
#pragma unroll 8
        for (int j = 0; j < 64; j++) {
            float wv = sWh[j][d];
            acc0 = fmaf(p0[j], wv, acc0);
            acc1 = fmaf(p1[j], wv, acc1);
        }
        __syncthreads();
    }

    {
        float v0 = acc0 / ssum[2 * g];
        float v1 = acc1 / ssum[2 * g + 1];
        if (do_relu) { v0 = fmaxf(v0, 0.f); v1 = fmaxf(v1, 0.f); }
        out[(size_t)(b * NNODES + i0 + 2 * g) * HID + d]     = v0;
        out[(size_t)(b * NNODES + i0 + 2 * g + 1) * HID + d] = v1;
    }
}

// ---------------- Stage D: edge gather + MLP + sigmoid ----------------
__global__ void __launch_bounds__(64)
edge_mlp_kernel(const float* __restrict__ h, const int* __restrict__ eidx,
                const float* __restrict__ fc1w, const float* __restrict__ fc1b,
                const float* __restrict__ fc2w, const float* __restrict__ fc2b,
                float* __restrict__ out)
{
    __shared__ float she[128];
    __shared__ float sr[2];

    const int e   = blockIdx.x;
    const int b   = blockIdx.y;
    const int tid = threadIdx.x;

    const int i1 = eidx[2 * e];
    const int i2 = eidx[2 * e + 1];
    she[tid]      = h[((size_t)b * NNODES + i1) * HID + tid];
    she[64 + tid] = h[((size_t)b * NNODES + i2) * HID + tid];
    __syncthreads();

    float acc = fc1b[tid];
#pragma unroll 8
    for (int k = 0; k < 128; k++)
        acc = fmaf(she[k], fc1w[(size_t)k * 64 + tid], acc);
    acc = fmaxf(acc, 0.f);

    float v = acc * fc2w[tid];
#pragma unroll
    for (int o = 16; o; o >>= 1)
        v += __shfl_down_sync(0xffffffffu, v, o);
    if ((tid & 31) == 0) sr[tid >> 5] = v;
    __syncthreads();
    if (tid == 0) {
        float z = sr[0] + sr[1] + fc2b[0];
        out[(size_t)b * NEDGES + e] = 1.f / (1.f + expf(-z));
    }
}

// ---------------- launch ----------------
extern "C" void kernel_launch(void* const* d_in, const int* in_sizes, int n_in,
                              void* d_out, int out_size)
{
    const float* x    = (const float*)d_in[0];
    const int*   adj  = (const int*)  d_in[1];
    const int*   eidx = (const int*)  d_in[2];
    const float* w1   = (const float*)d_in[3];
    const float* b1   = (const float*)d_in[4];
    const float* w2   = (const float*)d_in[5];
    const float* b2   = (const float*)d_in[6];
    const float* W1   = (const float*)d_in[7];
    const float* a1   = (const float*)d_in[8];
    const float* W2   = (const float*)d_in[9];
    const float* a2   = (const float*)d_in[10];
    const float* fc1w = (const float*)d_in[11];
    const float* fc1b = (const float*)d_in[12];
    const float* fc2w = (const float*)d_in[13];
    const float* fc2b = (const float*)d_in[14];
    float* out = (float*)d_out;

    float *h0, *Wh, *h1, *h2, *f1, *f2;
    cudaGetSymbolAddress((void**)&h0, g_h0);
    cudaGetSymbolAddress((void**)&Wh, g_Wh);
    cudaGetSymbolAddress((void**)&h1, g_h1);
    cudaGetSymbolAddress((void**)&h2, g_h2);
    cudaGetSymbolAddress((void**)&f1, g_f1);
    cudaGetSymbolAddress((void**)&f2, g_f2);

    cudaFuncSetAttribute(conv_fused_kernel,
                         cudaFuncAttributeMaxDynamicSharedMemorySize,
                         CONV_SMEM_BYTES);

    // Stage A: conv feature extractor (bf16 tensor-core implicit GEMM, padded tap)
    conv_fused_kernel<<<BATCH * NNODES, 256, CONV_SMEM_BYTES>>>(x, w1, b1, w2, b2, h0);

    // GAT layer 1 (relu on output)
    gat_pre_kernel<<<(BATCH * NNODES) / 16, 256>>>(h0, W1, a1, Wh, f1, f2);
    gat_att_kernel<<<(BATCH * NNODES) / 8, 256>>>(Wh, f1, f2, adj, h1, 1);

    // GAT layer 2 (no relu)
    gat_pre_kernel<<<(BATCH * NNODES) / 16, 256>>>(h1, W2, a2, Wh, f1, f2);
    gat_att_kernel<<<(BATCH * NNODES) / 8, 256>>>(Wh, f1, f2, adj, h2, 0);

    // Edge MLP
    dim3 eg(NEDGES, BATCH);
    edge_mlp_kernel<<<eg, 64>>>(h2, eidx, fc1w, fc1b, fc2w, fc2b, out);
}

// round 7
// speedup vs baseline: 1.3065x; 1.2552x over previous
#include <cuda_runtime.h>
#include <math.h>
#include <stdint.h>

#define BATCH   8
#define SEQ     200
#define NNODES  512
#define HID     64
#define NEDGES  2048
#define ALPHA   0.2f
#define NEGBIG  -9.0e15f

// ---------------- scratch (device globals, no allocation) ----------------
__device__ float g_h0[BATCH * NNODES * HID];
__device__ float g_Wh[BATCH * NNODES * HID];
__device__ float g_h1[BATCH * NNODES * HID];
__device__ float g_h2[BATCH * NNODES * HID];
__device__ float g_f1[BATCH * NNODES];
__device__ float g_f2[BATCH * NNODES];

// ---------------- tf32 helpers ----------------
__device__ __forceinline__ uint32_t f2tf32(float f) {
    uint32_t r;
    asm("cvt.rna.tf32.f32 %0, %1;" : "=r"(r) : "f"(f));
    return r;
}
__device__ __forceinline__ void mma_tf32(float* c,
                                         uint32_t a0, uint32_t a1, uint32_t a2, uint32_t a3,
                                         uint32_t b0, uint32_t b1) {
    asm volatile(
        "mma.sync.aligned.m16n8k8.row.col.f32.tf32.tf32.f32 "
        "{%0,%1,%2,%3}, {%4,%5,%6,%7}, {%8,%9}, {%0,%1,%2,%3};"
        : "+f"(c[0]), "+f"(c[1]), "+f"(c[2]), "+f"(c[3])
        : "r"(a0), "r"(a1), "r"(a2), "r"(a3), "r"(b0), "r"(b1));
}

// ---------------- Stage A: conv1+relu, conv2 as tf32 implicit GEMM ----
// One block per (b,n), 256 threads = 8 warps.
// GEMM: M = 208 rows (13 m16 tiles; warp covers tiles {warp, warp+8} if <13),
//       N = 64 output channels (8 n8 tiles), K = 160 (20 k8 chunks).
// A[s][r] = h1_tf32[ic][s+k]  (im2col from smem, r = ic*5+k)
// B[r][n] = w2_tf32[n][r]     (smem, row padded to 72 -> conflict-free frags)
#define H1W   264
#define W2P   72
#define S_H1_OFF  0
#define S_W2_OFF  (32 * H1W)                  // 8448
#define S_IN_OFF  (S_W2_OFF + 160 * W2P)      // 19968
#define S_W1_OFF  (S_IN_OFF + 2 * 208)        // 20384
#define S_RED_OFF (S_W1_OFF + 320)            // 20704
#define CONV_SMEM_FLOATS (S_RED_OFF + 8 * 64) // 21216
#define CONV_SMEM_BYTES  (CONV_SMEM_FLOATS * 4)

__global__ void __launch_bounds__(256, 2)
conv_fused_kernel(const float* __restrict__ x,
                  const float* __restrict__ w1, const float* __restrict__ b1,
                  const float* __restrict__ w2, const float* __restrict__ b2,
                  float* __restrict__ h0)
{
    extern __shared__ float sm[];
    float* s_h1  = sm + S_H1_OFF;   // tf32 bits stored as float
    float* s_w2  = sm + S_W2_OFF;   // tf32 bits
    float* s_in  = sm + S_IN_OFF;
    float* s_w1  = sm + S_W1_OFF;
    float* s_red = sm + S_RED_OFF;

    const int bn  = blockIdx.x;
    const int b   = bn >> 9;
    const int n   = bn & 511;
    const int tid = threadIdx.x;

    // ---- phase 0: weights + input, single barrier ----
    for (int i = tid; i < 320; i += 256) s_w1[i] = w1[i];

    // w2 transposed to [r][n] tf32, row stride 72
    for (int i = tid; i < 160 * 64; i += 256) {
        int nn = i / 160;
        int r  = i - nn * 160;
        ((uint32_t*)s_w2)[r * W2P + nn] = f2tf32(w2[nn * 160 + r]);
    }

    // input pads (2 each side per channel)
    if (tid < 8) {
        int c = tid >> 2, q = tid & 3;
        s_in[c * 208 + ((q & 1) ? 206 : 0) + (q >> 1)] = 0.f;
    }
    // input: xf[bn][c][s] = x[b, s, 2n+c]
    const float* xb = x + (size_t)b * SEQ * (NNODES * 2) + 2 * n;
    for (int i = tid; i < 2 * SEQ; i += 256) {
        int s = i >> 1, c = i & 1;
        s_in[c * 208 + 2 + s] = xb[(size_t)s * (NNODES * 2) + c];
    }
    __syncthreads();

    // ---- conv1 + relu -> tf32 h1, contiguous 25-pos runs (sliding window) ----
    {
        const int ic = tid >> 3;       // 32 channels
        const int j  = tid & 7;        // 8 position groups
        const int s0 = 25 * j;
        const float b1i = b1[ic];
        const float* w  = s_w1 + ic * 10;
        uint32_t* h1u = (uint32_t*)(s_h1 + ic * H1W);

        float a0[29], a1[29];
        const float* i0 = s_in + s0;
        const float* i1 = s_in + 208 + s0;
#pragma unroll
        for (int q = 0; q < 29; q++) { a0[q] = i0[q]; a1[q] = i1[q]; }

#pragma unroll
        for (int q = 0; q < 25; q++) {
            float acc = b1i;
#pragma unroll
            for (int k = 0; k < 5; k++)
                acc = fmaf(w[k], a0[q + k], fmaf(w[5 + k], a1[q + k], acc));
            h1u[2 + s0 + q] = f2tf32(fmaxf(acc, 0.f));
        }

        // pads: words [0,1] and [202,212) per ic row (MMA reads words 0..211)
        if (j == 0) { h1u[0] = 0u; h1u[1] = 0u; }
        if (j == 7) {
#pragma unroll
            for (int q = 0; q < 10; q++) h1u[202 + q] = 0u;
        }
    }
    __syncthreads();

    // -------- tensor-core GEMM (identical to R3) --------
    const int warp = tid >> 5;
    const int lane = tid & 31;
    const int g    = lane >> 2;
    const int t4   = lane & 3;

    const uint32_t* h1u = (const uint32_t*)s_h1;
    const uint32_t* w2u = (const uint32_t*)s_w2;

    float c[2][8][4];
#pragma unroll
    for (int mt = 0; mt < 2; mt++)
#pragma unroll
        for (int nt = 0; nt < 8; nt++)
#pragma unroll
            for (int q = 0; q < 4; q++) c[mt][nt][q] = 0.f;

    for (int kc = 0; kc < 20; kc++) {
        const int r0 = kc * 8 + t4;
        const int r1 = r0 + 4;
        const int ic0 = r0 / 5, k0 = r0 - ic0 * 5;
        const int ic1 = r1 / 5, k1 = r1 - ic1 * 5;

        uint32_t bb0[8], bb1[8];
#pragma unroll
        for (int nt = 0; nt < 8; nt++) {
            bb0[nt] = w2u[r0 * W2P + nt * 8 + g];
            bb1[nt] = w2u[r1 * W2P + nt * 8 + g];
        }

        const int ao0 = ic0 * H1W + k0;
        const int ao1 = ic1 * H1W + k1;
#pragma unroll
        for (int mt = 0; mt < 2; mt++) {
            const int tile = warp + 8 * mt;
            if (tile >= 13) continue;
            const int sb = tile * 16 + g;
            uint32_t a0 = h1u[ao0 + sb];
            uint32_t a1 = h1u[ao0 + sb + 8];
            uint32_t a2 = h1u[ao1 + sb];
            uint32_t a3 = h1u[ao1 + sb + 8];
#pragma unroll
            for (int nt = 0; nt < 8; nt++)
                mma_tf32(c[mt][nt], a0, a1, a2, a3, bb0[nt], bb1[nt]);
        }
    }

    // -------- epilogue: bias + relu + masked sum over positions --------
#pragma unroll
    for (int nt = 0; nt < 8; nt++) {
        const int n0 = nt * 8 + 2 * t4;
        const float bias0 = b2[n0], bias1 = b2[n0 + 1];
        float s0 = 0.f, s1 = 0.f;
#pragma unroll
        for (int mt = 0; mt < 2; mt++) {
            const int tile = warp + 8 * mt;
            if (tile >= 13) continue;
            const int rA = tile * 16 + g;
            const int rB = rA + 8;
            if (rA < 200) {
                s0 += fmaxf(c[mt][nt][0] + bias0, 0.f);
                s1 += fmaxf(c[mt][nt][1] + bias1, 0.f);
            }
            if (rB < 200) {
                s0 += fmaxf(c[mt][nt][2] + bias0, 0.f);
                s1 += fmaxf(c[mt][nt][3] + bias1, 0.f);
            }
        }
#pragma unroll
        for (int off = 16; off >= 4; off >>= 1) {
            s0 += __shfl_down_sync(0xffffffffu, s0, off);
            s1 += __shfl_down_sync(0xffffffffu, s1, off);
        }
        if (lane < 4) {
            s_red[warp * 64 + nt * 8 + 2 * lane]     = s0;
            s_red[warp * 64 + nt * 8 + 2 * lane + 1] = s1;
        }
    }
    __syncthreads();

    if (tid < 64) {
        float t = 0.f;
#pragma unroll
        for (int w = 0; w < 8; w++) t += s_red[w * 64 + tid];
        h0[(size_t)bn * HID + tid] = t * (1.f / 200.f);
    }
}

// ---------------- Stage B: Wh = h @ W ; f1 = Wh@a[:64] ; f2 = Wh@a[64:] ----
__global__ void __launch_bounds__(256)
gat_pre_kernel(const float* __restrict__ h, const float* __restrict__ W,
               const float* __restrict__ a,
               float* __restrict__ Wh, float* __restrict__ f1, float* __restrict__ f2)
{
    __shared__ float sW[64 * 64];
    __shared__ float sh[16 * 64];
    __shared__ float s1[8][4], s2[8][4];

    const int tid  = threadIdx.x;
    const int row0 = blockIdx.x * 16;

    for (int i = tid; i < 64 * 64; i += 256) sW[i] = W[i];
    for (int i = tid; i < 16 * 64; i += 256) sh[i] = h[(size_t)row0 * 64 + i];
    __syncthreads();

    const int rg = tid >> 6;
    const int d  = tid & 63;
    float acc[4] = {0.f, 0.f, 0.f, 0.f};
#pragma unroll 8
    for (int k = 0; k < 64; k++) {
        float w = sW[k * 64 + d];
#pragma unroll
        for (int j = 0; j < 4; j++)
            acc[j] = fmaf(sh[(rg * 4 + j) * 64 + k], w, acc[j]);
    }
    const float a1v = a[d], a2v = a[64 + d];
    float v1[4], v2[4];
#pragma unroll
    for (int j = 0; j < 4; j++) {
        Wh[(size_t)(row0 + rg * 4 + j) * 64 + d] = acc[j];
        v1[j] = acc[j] * a1v;
        v2[j] = acc[j] * a2v;
    }
#pragma unroll
    for (int o = 16; o; o >>= 1)
#pragma unroll
        for (int j = 0; j < 4; j++) {
            v1[j] += __shfl_down_sync(0xffffffffu, v1[j], o);
            v2[j] += __shfl_down_sync(0xffffffffu, v2[j], o);
        }
    const int w = tid >> 5;
    if ((tid & 31) == 0)
#pragma unroll
        for (int j = 0; j < 4; j++) { s1[w][j] = v1[j]; s2[w][j] = v2[j]; }
    __syncthreads();
    if (tid < 16) {
        int gq = tid >> 2, j = tid & 3;
        f1[row0 + gq * 4 + j] = s1[2 * gq][j] + s1[2 * gq + 1][j];
        f2[row0 + gq * 4 + j] = s2[2 * gq][j] + s2[2 * gq + 1][j];
    }
}

// ---------------- Stage C: attention, 8 rows per block, j-tiled Wh ----------
__global__ void __launch_bounds__(256)
gat_att_kernel(const float* __restrict__ Wh, const float* __restrict__ f1,
               const float* __restrict__ f2, const int* __restrict__ adj,
               float* __restrict__ out, int do_relu)
{
    __shared__ float sp[8][512];
    __shared__ float sWh[64][65];
    __shared__ float ssum[8];

    const int blk = blockIdx.x;
    const int b   = blk >> 6;
    const int i0  = (blk & 63) * 8;
    const int tid = threadIdx.x;
    const int w   = tid >> 5;
    const int ln  = tid & 31;

    {
        const int i  = i0 + w;
        const int bi = b * NNODES + i;
        const float f1i = f1[bi];
        const float* f2b = f2 + b * NNODES;
        const int* adjrow = adj + (size_t)i * NNODES;

        float ev[16];
        float lmax = -3.4e38f;
#pragma unroll
        for (int t = 0; t < 16; t++) {
            int j = ln + t * 32;
            float e = f1i + f2b[j];
            e = (e > 0.f) ? e : ALPHA * e;
            e = (adjrow[j] > 0) ? e : NEGBIG;
            ev[t] = e;
            lmax = fmaxf(lmax, e);
        }
#pragma unroll
        for (int o = 16; o; o >>= 1)
            lmax = fmaxf(lmax, __shfl_xor_sync(0xffffffffu, lmax, o));
        float lsum = 0.f;
#pragma unroll
        for (int t = 0; t < 16; t++) {
            float p = expf(ev[t] - lmax);
            sp[w][ln + t * 32] = p;
            lsum += p;
        }
#pragma unroll
        for (int o = 16; o; o >>= 1)
            lsum += __shfl_xor_sync(0xffffffffu, lsum, o);
        if (ln == 0) ssum[w] = lsum;
    }
    __syncthreads();

    const int g = tid >> 6;
    const int d = tid & 63;
    const float* Whb = Wh + (size_t)b * NNODES * HID;
    float acc0 = 0.f, acc1 = 0.f;

    for (int jt = 0; jt < 8; jt++) {
#pragma unroll
        for (int t = 0; t < 16; t++) {
            int idx = tid + t * 256;
            int j = idx >> 6, dd = idx & 63;
            sWh[j][dd] = Whb[(size_t)(jt * 64 + j) * 64 + dd];
        }
        __syncthreads();
        const float* p0 = &sp[2 * g][jt * 64];
        const float* p1 = &sp[2 * g + 1][jt * 64];
#pragma unroll 8
        for (int j = 0; j < 64; j++) {
            float wv = sWh[j][d];
            acc0 = fmaf(p0[j], wv, acc0);
            acc1 = fmaf(p1[j], wv, acc1);
        }
        __syncthreads();
    }

    {
        float v0 = acc0 / ssum[2 * g];
        float v1 = acc1 / ssum[2 * g + 1];
        if (do_relu) { v0 = fmaxf(v0, 0.f); v1 = fmaxf(v1, 0.f); }
        out[(size_t)(b * NNODES + i0 + 2 * g) * HID + d]     = v0;
        out[(size_t)(b * NNODES + i0 + 2 * g + 1) * HID + d] = v1;
    }
}

// ---------------- Stage D: edge gather + MLP + sigmoid ----------------
__global__ void __launch_bounds__(64)
edge_mlp_kernel(const float* __restrict__ h, const int* __restrict__ eidx,
                const float* __restrict__ fc1w, const float* __restrict__ fc1b,
                const float* __restrict__ fc2w, const float* __restrict__ fc2b,
                float* __restrict__ out)
{
    __shared__ float she[128];
    __shared__ float sr[2];

    const int e   = blockIdx.x;
    const int b   = blockIdx.y;
    const int tid = threadIdx.x;

    const int i1 = eidx[2 * e];
    const int i2 = eidx[2 * e + 1];
    she[tid]      = h[((size_t)b * NNODES + i1) * HID + tid];
    she[64 + tid] = h[((size_t)b * NNODES + i2) * HID + tid];
    __syncthreads();

    float acc = fc1b[tid];
#pragma unroll 8
    for (int k = 0; k < 128; k++)
        acc = fmaf(she[k], fc1w[(size_t)k * 64 + tid], acc);
    acc = fmaxf(acc, 0.f);

    float v = acc * fc2w[tid];
#pragma unroll
    for (int o = 16; o; o >>= 1)
        v += __shfl_down_sync(0xffffffffu, v, o);
    if ((tid & 31) == 0) sr[tid >> 5] = v;
    __syncthreads();
    if (tid == 0) {
        float z = sr[0] + sr[1] + fc2b[0];
        out[(size_t)b * NEDGES + e] = 1.f / (1.f + expf(-z));
    }
}

// ---------------- launch ----------------
extern "C" void kernel_launch(void* const* d_in, const int* in_sizes, int n_in,
                              void* d_out, int out_size)
{
    const float* x    = (const float*)d_in[0];
    const int*   adj  = (const int*)  d_in[1];
    const int*   eidx = (const int*)  d_in[2];
    const float* w1   = (const float*)d_in[3];
    const float* b1   = (const float*)d_in[4];
    const float* w2   = (const float*)d_in[5];
    const float* b2   = (const float*)d_in[6];
    const float* W1   = (const float*)d_in[7];
    const float* a1   = (const float*)d_in[8];
    const float* W2   = (const float*)d_in[9];
    const float* a2   = (const float*)d_in[10];
    const float* fc1w = (const float*)d_in[11];
    const float* fc1b = (const float*)d_in[12];
    const float* fc2w = (const float*)d_in[13];
    const float* fc2b = (const float*)d_in[14];
    float* out = (float*)d_out;

    float *h0, *Wh, *h1, *h2, *f1, *f2;
    cudaGetSymbolAddress((void**)&h0, g_h0);
    cudaGetSymbolAddress((void**)&Wh, g_Wh);
    cudaGetSymbolAddress((void**)&h1, g_h1);
    cudaGetSymbolAddress((void**)&h2, g_h2);
    cudaGetSymbolAddress((void**)&f1, g_f1);
    cudaGetSymbolAddress((void**)&f2, g_f2);

    cudaFuncSetAttribute(conv_fused_kernel,
                         cudaFuncAttributeMaxDynamicSharedMemorySize,
                         CONV_SMEM_BYTES);

    // Stage A: conv feature extractor (tf32 implicit GEMM, sliding-window conv1)
    conv_fused_kernel<<<BATCH * NNODES, 256, CONV_SMEM_BYTES>>>(x, w1, b1, w2, b2, h0);

    // GAT layer 1 (relu on output)
    gat_pre_kernel<<<(BATCH * NNODES) / 16, 256>>>(h0, W1, a1, Wh, f1, f2);
    gat_att_kernel<<<(BATCH * NNODES) / 8, 256>>>(Wh, f1, f2, adj, h1, 1);

    // GAT layer 2 (no relu)
    gat_pre_kernel<<<(BATCH * NNODES) / 16, 256>>>(h1, W2, a2, Wh, f1, f2);
    gat_att_kernel<<<(BATCH * NNODES) / 8, 256>>>(Wh, f1, f2, adj, h2, 0);

    // Edge MLP
    dim3 eg(NEDGES, BATCH);
    edge_mlp_kernel<<<eg, 64>>>(h2, eidx, fc1w, fc1b, fc2w, fc2b, out);
}

// round 8
// speedup vs baseline: 1.5431x; 1.1811x over previous
#include <cuda_runtime.h>
#include <math.h>
#include <stdint.h>

#define BATCH   8
#define SEQ     200
#define NNODES  512
#define HID     64
#define NEDGES  2048
#define ALPHA   0.2f
#define NEGBIG  -9.0e15f

// ---------------- scratch (device globals, no allocation) ----------------
__device__ float g_Wh1[BATCH * NNODES * HID];
__device__ float g_Wh2[BATCH * NNODES * HID];
__device__ float g_h2[BATCH * NNODES * HID];
__device__ float g_f1a[BATCH * NNODES];
__device__ float g_f2a[BATCH * NNODES];
__device__ float g_f1b[BATCH * NNODES];
__device__ float g_f2b[BATCH * NNODES];
__device__ uint4 g_w2t[160 * 72 / 4];     // tf32, [r][n] transposed, stride 72

// ---------------- tf32 helpers ----------------
__device__ __forceinline__ uint32_t f2tf32(float f) {
    uint32_t r;
    asm("cvt.rna.tf32.f32 %0, %1;" : "=r"(r) : "f"(f));
    return r;
}
__device__ __forceinline__ void mma_tf32(float* c,
                                         uint32_t a0, uint32_t a1, uint32_t a2, uint32_t a3,
                                         uint32_t b0, uint32_t b1) {
    asm volatile(
        "mma.sync.aligned.m16n8k8.row.col.f32.tf32.tf32.f32 "
        "{%0,%1,%2,%3}, {%4,%5,%6,%7}, {%8,%9}, {%0,%1,%2,%3};"
        : "+f"(c[0]), "+f"(c[1]), "+f"(c[2]), "+f"(c[3])
        : "r"(a0), "r"(a1), "r"(a2), "r"(a3), "r"(b0), "r"(b1));
}

// ---------------- setup: pre-convert conv2 weights ----------------
__global__ void pack_w2_kernel(const float* __restrict__ w2) {
    int i = blockIdx.x * blockDim.x + threadIdx.x;
    if (i >= 160 * 72) return;
    int r = i / 72, nn = i - r * 72;
    uint32_t v = (nn < 64) ? f2tf32(w2[nn * 160 + r]) : 0u;
    ((uint32_t*)g_w2t)[r * 72 + nn] = v;
}

// ---------------- Stage A: conv (2 nodes/block) + fused gat_pre1 ----------
#define H1W   264
#define W2P   72
#define S_H1_OFF  0
#define S_W2_OFF  (32 * H1W)                  // 8448
#define S_IN_OFF  (S_W2_OFF + 160 * W2P)      // 19968
#define S_W1_OFF  (S_IN_OFF + 2 * 208)        // 20384
#define S_RED_OFF (S_W1_OFF + 320)            // 20704
#define S_H0_OFF  (S_RED_OFF + 512)           // 21216
#define S_PT_OFF  (S_H0_OFF + 64)             // 21280
#define CONV_SMEM_FLOATS (S_PT_OFF + 256)     // 21536
#define CONV_SMEM_BYTES  (CONV_SMEM_FLOATS * 4)

__global__ void __launch_bounds__(256, 2)
conv_fused_kernel(const float* __restrict__ x,
                  const float* __restrict__ w1, const float* __restrict__ b1,
                  const float* __restrict__ b2,
                  const float* __restrict__ W1, const float* __restrict__ a1,
                  float* __restrict__ Wh, float* __restrict__ f1, float* __restrict__ f2)
{
    extern __shared__ float sm[];
    float* s_h1  = sm + S_H1_OFF;
    float* s_w2  = sm + S_W2_OFF;
    float* s_in  = sm + S_IN_OFF;
    float* s_w1  = sm + S_W1_OFF;
    float* s_red = sm + S_RED_OFF;
    float* s_h0  = sm + S_H0_OFF;
    float* s_pt  = sm + S_PT_OFF;

    const int tid = threadIdx.x;

    // one-time: conv1 weights + pre-converted w2 (uint4 copy)
    for (int i = tid; i < 320; i += 256) s_w1[i] = w1[i];
    {
        uint4* dst = (uint4*)s_w2;
        for (int i = tid; i < 2880; i += 256) dst[i] = g_w2t[i];
    }
    if (tid < 8) {
        int c = tid >> 2, q = tid & 3;
        s_in[c * 208 + ((q & 1) ? 206 : 0) + (q >> 1)] = 0.f;
    }

    const int warp = tid >> 5;
    const int lane = tid & 31;
    const int g    = lane >> 2;
    const int t4   = lane & 3;

    for (int half = 0; half < 2; half++) {
        const int bn = blockIdx.x * 2 + half;
        const int b  = bn >> 9;
        const int n  = bn & 511;

        // input: xf[bn][c][s] = x[b, s, 2n+c]
        const float* xb = x + (size_t)b * SEQ * (NNODES * 2) + 2 * n;
        for (int i = tid; i < 2 * SEQ; i += 256) {
            int s = i >> 1, c = i & 1;
            s_in[c * 208 + 2 + s] = xb[(size_t)s * (NNODES * 2) + c];
        }
        __syncthreads();

        // conv1 + relu -> tf32 h1, sliding-window 25-pos runs
        {
            const int ic = tid >> 3;
            const int j  = tid & 7;
            const int s0 = 25 * j;
            const float b1i = b1[ic];
            const float* w  = s_w1 + ic * 10;
            uint32_t* h1u = (uint32_t*)(s_h1 + ic * H1W);

            float a0[29], a1v[29];
            const float* i0 = s_in + s0;
            const float* i1 = s_in + 208 + s0;
#pragma unroll
            for (int q = 0; q < 29; q++) { a0[q] = i0[q]; a1v[q] = i1[q]; }

#pragma unroll
            for (int q = 0; q < 25; q++) {
                float acc = b1i;
#pragma unroll
                for (int k = 0; k < 5; k++)
                    acc = fmaf(w[k], a0[q + k], fmaf(w[5 + k], a1v[q + k], acc));
                h1u[2 + s0 + q] = f2tf32(fmaxf(acc, 0.f));
            }
            if (j == 0) { h1u[0] = 0u; h1u[1] = 0u; }
            if (j == 7) {
#pragma unroll
                for (int q = 0; q < 10; q++) h1u[202 + q] = 0u;
            }
        }
        __syncthreads();

        // -------- tensor-core GEMM --------
        const uint32_t* h1u = (const uint32_t*)s_h1;
        const uint32_t* w2u = (const uint32_t*)s_w2;

        float c[2][8][4];
#pragma unroll
        for (int mt = 0; mt < 2; mt++)
#pragma unroll
            for (int nt = 0; nt < 8; nt++)
#pragma unroll
                for (int q = 0; q < 4; q++) c[mt][nt][q] = 0.f;

        for (int kc = 0; kc < 20; kc++) {
            const int r0 = kc * 8 + t4;
            const int r1 = r0 + 4;
            const int ic0 = r0 / 5, k0 = r0 - ic0 * 5;
            const int ic1 = r1 / 5, k1 = r1 - ic1 * 5;

            uint32_t bb0[8], bb1[8];
#pragma unroll
            for (int nt = 0; nt < 8; nt++) {
                bb0[nt] = w2u[r0 * W2P + nt * 8 + g];
                bb1[nt] = w2u[r1 * W2P + nt * 8 + g];
            }

            const int ao0 = ic0 * H1W + k0;
            const int ao1 = ic1 * H1W + k1;
#pragma unroll
            for (int mt = 0; mt < 2; mt++) {
                const int tile = warp + 8 * mt;
                if (tile >= 13) continue;
                const int sb = tile * 16 + g;
                uint32_t a0 = h1u[ao0 + sb];
                uint32_t a1 = h1u[ao0 + sb + 8];
                uint32_t a2 = h1u[ao1 + sb];
                uint32_t a3 = h1u[ao1 + sb + 8];
#pragma unroll
                for (int nt = 0; nt < 8; nt++)
                    mma_tf32(c[mt][nt], a0, a1, a2, a3, bb0[nt], bb1[nt]);
            }
        }

        // -------- epilogue: bias + relu + masked sum over positions --------
#pragma unroll
        for (int nt = 0; nt < 8; nt++) {
            const int n0 = nt * 8 + 2 * t4;
            const float bias0 = b2[n0], bias1 = b2[n0 + 1];
            float s0 = 0.f, s1 = 0.f;
#pragma unroll
            for (int mt = 0; mt < 2; mt++) {
                const int tile = warp + 8 * mt;
                if (tile >= 13) continue;
                const int rA = tile * 16 + g;
                const int rB = rA + 8;
                if (rA < 200) {
                    s0 += fmaxf(c[mt][nt][0] + bias0, 0.f);
                    s1 += fmaxf(c[mt][nt][1] + bias1, 0.f);
                }
                if (rB < 200) {
                    s0 += fmaxf(c[mt][nt][2] + bias0, 0.f);
                    s1 += fmaxf(c[mt][nt][3] + bias1, 0.f);
                }
            }
#pragma unroll
            for (int off = 16; off >= 4; off >>= 1) {
                s0 += __shfl_down_sync(0xffffffffu, s0, off);
                s1 += __shfl_down_sync(0xffffffffu, s1, off);
            }
            if (lane < 4) {
                s_red[warp * 64 + nt * 8 + 2 * lane]     = s0;
                s_red[warp * 64 + nt * 8 + 2 * lane + 1] = s1;
            }
        }
        __syncthreads();

        if (tid < 64) {
            float t = 0.f;
#pragma unroll
            for (int w = 0; w < 8; w++) t += s_red[w * 64 + tid];
            s_h0[tid] = t * (1.f / 200.f);
        }
        __syncthreads();

        // -------- fused gat_pre1: Wh1 = h0 @ W1 ; f1 ; f2 --------
        {
            const int kq = tid >> 6;
            const int d  = tid & 63;
            float acc = 0.f;
#pragma unroll
            for (int i = 0; i < 16; i++) {
                int k = kq * 16 + i;
                acc = fmaf(s_h0[k], __ldg(W1 + k * 64 + d), acc);
            }
            s_pt[kq * 64 + d] = acc;
        }
        __syncthreads();

        if (tid < 64) {
            float wh = s_pt[tid] + s_pt[64 + tid] + s_pt[128 + tid] + s_pt[192 + tid];
            Wh[(size_t)bn * 64 + tid] = wh;
            float v1 = wh * __ldg(a1 + tid);
            float v2 = wh * __ldg(a1 + 64 + tid);
#pragma unroll
            for (int o = 16; o; o >>= 1) {
                v1 += __shfl_down_sync(0xffffffffu, v1, o);
                v2 += __shfl_down_sync(0xffffffffu, v2, o);
            }
            if ((tid & 31) == 0) {
                s_pt[(tid >> 5) * 2]     = v1;
                s_pt[(tid >> 5) * 2 + 1] = v2;
            }
        }
        __syncthreads();
        if (tid == 0) {
            f1[bn] = s_pt[0] + s_pt[2];
            f2[bn] = s_pt[1] + s_pt[3];
        }
        __syncthreads();
    }
}

// ---------------- Stage B: attention layer1 + fused gat_pre2 ----------
// grid = 512 blocks x 256 threads; 8 rows per block.
__global__ void __launch_bounds__(256)
gat_att1_kernel(const float* __restrict__ Wh, const float* __restrict__ f1,
                const float* __restrict__ f2, const int* __restrict__ adj,
                const float* __restrict__ W2, const float* __restrict__ a2,
                float* __restrict__ Wh2, float* __restrict__ f1o, float* __restrict__ f2o)
{
    __shared__ float sp[8][512];
    __shared__ float sWh[64][65];
    __shared__ float s_hl[8][64];
    __shared__ float ssum[8];
    __shared__ float s_r2[8][4];

    const int blk = blockIdx.x;
    const int b   = blk >> 6;
    const int i0  = (blk & 63) * 8;
    const int tid = threadIdx.x;
    const int w   = tid >> 5;
    const int ln  = tid & 31;

    // phase A: softmax numerators (one warp per row)
    {
        const int i  = i0 + w;
        const int bi = b * NNODES + i;
        const float f1i = f1[bi];
        const float* f2b = f2 + b * NNODES;
        const int* adjrow = adj + (size_t)i * NNODES;

        float ev[16];
        float lmax = -3.4e38f;
#pragma unroll
        for (int t = 0; t < 16; t++) {
            int j = ln + t * 32;
            float e = f1i + f2b[j];
            e = (e > 0.f) ? e : ALPHA * e;
            e = (adjrow[j] > 0) ? e : NEGBIG;
            ev[t] = e;
            lmax = fmaxf(lmax, e);
        }
#pragma unroll
        for (int o = 16; o; o >>= 1)
            lmax = fmaxf(lmax, __shfl_xor_sync(0xffffffffu, lmax, o));
        float lsum = 0.f;
#pragma unroll
        for (int t = 0; t < 16; t++) {
            float p = expf(ev[t] - lmax);
            sp[w][ln + t * 32] = p;
            lsum += p;
        }
#pragma unroll
        for (int o = 16; o; o >>= 1)
            lsum += __shfl_xor_sync(0xffffffffu, lsum, o);
        if (ln == 0) ssum[w] = lsum;
    }
    __syncthreads();

    // phase B: aggregate Wh rows, j tiled by 64
    const int g = tid >> 6;
    const int d = tid & 63;
    const float* Whb = Wh + (size_t)b * NNODES * HID;
    float acc0 = 0.f, acc1 = 0.f;

    for (int jt = 0; jt < 8; jt++) {
#pragma unroll
        for (int t = 0; t < 16; t++) {
            int idx = tid + t * 256;
            int j = idx >> 6, dd = idx & 63;
            sWh[j][dd] = Whb[(size_t)(jt * 64 + j) * 64 + dd];
        }
        __syncthreads();
        const float* p0 = &sp[2 * g][jt * 64];
        const float* p1 = &sp[2 * g + 1][jt * 64];
#pragma unroll 8
        for (int j = 0; j < 64; j++) {
            float wv = sWh[j][d];
            acc0 = fmaf(p0[j], wv, acc0);
            acc1 = fmaf(p1[j], wv, acc1);
        }
        __syncthreads();
    }

    // h1 rows (relu) -> smem
    s_hl[2 * g][d]     = fmaxf(acc0 / ssum[2 * g], 0.f);
    s_hl[2 * g + 1][d] = fmaxf(acc1 / ssum[2 * g + 1], 0.f);

    // load W2 into sWh
#pragma unroll
    for (int t = 0; t < 16; t++) {
        int idx = tid + t * 256;
        sWh[idx >> 6][idx & 63] = W2[idx];
    }
    __syncthreads();

    // fused gat_pre2: Wh2 rows + f1/f2
    {
        float wh0 = 0.f, wh1 = 0.f;
        const float* h0r = s_hl[2 * g];
        const float* h1r = s_hl[2 * g + 1];
#pragma unroll 8
        for (int k = 0; k < 64; k++) {
            float wv = sWh[k][d];
            wh0 = fmaf(h0r[k], wv, wh0);
            wh1 = fmaf(h1r[k], wv, wh1);
        }
        const int row0 = b * NNODES + i0 + 2 * g;
        Wh2[(size_t)row0 * 64 + d]       = wh0;
        Wh2[(size_t)(row0 + 1) * 64 + d] = wh1;

        const float a2d = __ldg(a2 + d);
        const float a2e = __ldg(a2 + 64 + d);
        float u0 = wh0 * a2d, v0 = wh0 * a2e;
        float u1 = wh1 * a2d, v1 = wh1 * a2e;
#pragma unroll
        for (int o = 16; o; o >>= 1) {
            u0 += __shfl_down_sync(0xffffffffu, u0, o);
            v0 += __shfl_down_sync(0xffffffffu, v0, o);
            u1 += __shfl_down_sync(0xffffffffu, u1, o);
            v1 += __shfl_down_sync(0xffffffffu, v1, o);
        }
        if (ln == 0) {
            s_r2[w][0] = u0; s_r2[w][1] = v0;
            s_r2[w][2] = u1; s_r2[w][3] = v1;
        }
    }
    __syncthreads();
    if (tid < 8) {
        int r = tid;               // local row
        int gg = r >> 1;           // group
        int j0 = (r & 1) ? 2 : 0;  // even/odd row within group
        float fa = s_r2[2 * gg][j0]     + s_r2[2 * gg + 1][j0];
        float fb = s_r2[2 * gg][j0 + 1] + s_r2[2 * gg + 1][j0 + 1];
        f1o[b * NNODES + i0 + r] = fa;
        f2o[b * NNODES + i0 + r] = fb;
    }
}

// ---------------- Stage C: attention layer2 (plain) ----------
__global__ void __launch_bounds__(256)
gat_att2_kernel(const float* __restrict__ Wh, const float* __restrict__ f1,
                const float* __restrict__ f2, const int* __restrict__ adj,
                float* __restrict__ out)
{
    __shared__ float sp[8][512];
    __shared__ float sWh[64][65];
    __shared__ float ssum[8];

    const int blk = blockIdx.x;
    const int b   = blk >> 6;
    const int i0  = (blk & 63) * 8;
    const int tid = threadIdx.x;
    const int w   = tid >> 5;
    const int ln  = tid & 31;

    {
        const int i  = i0 + w;
        const int bi = b * NNODES + i;
        const float f1i = f1[bi];
        const float* f2b = f2 + b * NNODES;
        const int* adjrow = adj + (size_t)i * NNODES;

        float ev[16];
        float lmax = -3.4e38f;
#pragma unroll
        for (int t = 0; t < 16; t++) {
            int j = ln + t * 32;
            float e = f1i + f2b[j];
            e = (e > 0.f) ? e : ALPHA * e;
            e = (adjrow[j] > 0) ? e : NEGBIG;
            ev[t] = e;
            lmax = fmaxf(lmax, e);
        }
#pragma unroll
        for (int o = 16; o; o >>= 1)
            lmax = fmaxf(lmax, __shfl_xor_sync(0xffffffffu, lmax, o));
        float lsum = 0.f;
#pragma unroll
        for (int t = 0; t < 16; t++) {
            float p = expf(ev[t] - lmax);
            sp[w][ln + t * 32] = p;
            lsum += p;
        }
#pragma unroll
        for (int o = 16; o; o >>= 1)
            lsum += __shfl_xor_sync(0xffffffffu, lsum, o);
        if (ln == 0) ssum[w] = lsum;
    }
    __syncthreads();

    const int g = tid >> 6;
    const int d = tid & 63;
    const float* Whb = Wh + (size_t)b * NNODES * HID;
    float acc0 = 0.f, acc1 = 0.f;

    for (int jt = 0; jt < 8; jt++) {
#pragma unroll
        for (int t = 0; t < 16; t++) {
            int idx = tid + t * 256;
            int j = idx >> 6, dd = idx & 63;
            sWh[j][dd] = Whb[(size_t)(jt * 64 + j) * 64 + dd];
        }
        __syncthreads();
        const float* p0 = &sp[2 * g][jt * 64];
        const float* p1 = &sp[2 * g + 1][jt * 64];
#pragma unroll 8
        for (int j = 0; j < 64; j++) {
            float wv = sWh[j][d];
            acc0 = fmaf(p0[j], wv, acc0);
            acc1 = fmaf(p1[j], wv, acc1);
        }
        __syncthreads();
    }

    out[(size_t)(b * NNODES + i0 + 2 * g) * HID + d]     = acc0 / ssum[2 * g];
    out[(size_t)(b * NNODES + i0 + 2 * g + 1) * HID + d] = acc1 / ssum[2 * g + 1];
}

// ---------------- Stage D: edge gather + MLP + sigmoid ----------------
__global__ void __launch_bounds__(64)
edge_mlp_kernel(const float* __restrict__ h, const int* __restrict__ eidx,
                const float* __restrict__ fc1w, const float* __restrict__ fc1b,
                const float* __restrict__ fc2w, const float* __restrict__ fc2b,
                float* __restrict__ out)
{
    __shared__ float she[128];
    __shared__ float sr[2];

    const int e   = blockIdx.x;
    const int b   = blockIdx.y;
    const int tid = threadIdx.x;

    const int i1 = eidx[2 * e];
    const int i2 = eidx[2 * e + 1];
    she[tid]      = h[((size_t)b * NNODES + i1) * HID + tid];
    she[64 + tid] = h[((size_t)b * NNODES + i2) * HID + tid];
    __syncthreads();

    float acc = fc1b[tid];
#pragma unroll 8
    for (int k = 0; k < 128; k++)
        acc = fmaf(she[k], fc1w[(size_t)k * 64 + tid], acc);
    acc = fmaxf(acc, 0.f);

    float v = acc * fc2w[tid];
#pragma unroll
    for (int o = 16; o; o >>= 1)
        v += __shfl_down_sync(0xffffffffu, v, o);
    if ((tid & 31) == 0) sr[tid >> 5] = v;
    __syncthreads();
    if (tid == 0) {
        float z = sr[0] + sr[1] + fc2b[0];
        out[(size_t)b * NEDGES + e] = 1.f / (1.f + expf(-z));
    }
}

// ---------------- launch ----------------
extern "C" void kernel_launch(void* const* d_in, const int* in_sizes, int n_in,
                              void* d_out, int out_size)
{
    const float* x    = (const float*)d_in[0];
    const int*   adj  = (const int*)  d_in[1];
    const int*   eidx = (const int*)  d_in[2];
    const float* w1   = (const float*)d_in[3];
    const float* b1   = (const float*)d_in[4];
    const float* w2   = (const float*)d_in[5];
    const float* b2   = (const float*)d_in[6];
    const float* W1   = (const float*)d_in[7];
    const float* a1   = (const float*)d_in[8];
    const float* W2   = (const float*)d_in[9];
    const float* a2   = (const float*)d_in[10];
    const float* fc1w = (const float*)d_in[11];
    const float* fc1b = (const float*)d_in[12];
    const float* fc2w = (const float*)d_in[13];
    const float* fc2b = (const float*)d_in[14];
    float* out = (float*)d_out;

    float *Wh1, *Wh2, *h2, *f1a, *f2a, *f1b, *f2b;
    cudaGetSymbolAddress((void**)&Wh1, g_Wh1);
    cudaGetSymbolAddress((void**)&Wh2, g_Wh2);
    cudaGetSymbolAddress((void**)&h2,  g_h2);
    cudaGetSymbolAddress((void**)&f1a, g_f1a);
    cudaGetSymbolAddress((void**)&f2a, g_f2a);
    cudaGetSymbolAddress((void**)&f1b, g_f1b);
    cudaGetSymbolAddress((void**)&f2b, g_f2b);

    cudaFuncSetAttribute(conv_fused_kernel,
                         cudaFuncAttributeMaxDynamicSharedMemorySize,
                         CONV_SMEM_BYTES);

    // setup: pre-convert conv2 weights to tf32 transposed layout
    pack_w2_kernel<<<(160 * 72 + 255) / 256, 256>>>(w2);

    // Stage A: conv (2 nodes/block) + fused Wh1/f1/f2
    conv_fused_kernel<<<(BATCH * NNODES) / 2, 256, CONV_SMEM_BYTES>>>(
        x, w1, b1, b2, W1, a1, Wh1, f1a, f2a);

    // Stage B: GAT layer 1 attention + fused Wh2/f1/f2 (h1 never hits HBM)
    gat_att1_kernel<<<(BATCH * NNODES) / 8, 256>>>(
        Wh1, f1a, f2a, adj, W2, a2, Wh2, f1b, f2b);

    // Stage C: GAT layer 2 attention
    gat_att2_kernel<<<(BATCH * NNODES) / 8, 256>>>(Wh2, f1b, f2b, adj, h2);

    // Stage D: edge MLP
    dim3 eg(NEDGES, BATCH);
    edge_mlp_kernel<<<eg, 64>>>(h2, eidx, fc1w, fc1b, fc2w, fc2b, out);
}

// round 9
// speedup vs baseline: 1.6572x; 1.0739x over previous
#include <cuda_runtime.h>
#include <math.h>
#include <stdint.h>

#define BATCH   8
#define SEQ     200
#define NNODES  512
#define HID     64
#define NEDGES  2048
#define ALPHA   0.2f
#define NEGBIG  -9.0e15f

// ---------------- scratch (device globals, no allocation) ----------------
__device__ float g_Wh1[BATCH * NNODES * HID];
__device__ float g_Wh2[BATCH * NNODES * HID];
__device__ float g_h2[BATCH * NNODES * HID];
__device__ float g_f1a[BATCH * NNODES];
__device__ float g_f2a[BATCH * NNODES];
__device__ float g_f1b[BATCH * NNODES];
__device__ float g_f2b[BATCH * NNODES];
__device__ uint4 g_w2t[160 * 72 / 4];     // tf32, [r][n] transposed, stride 72

// ---------------- tf32 helpers ----------------
__device__ __forceinline__ uint32_t f2tf32(float f) {
    uint32_t r;
    asm("cvt.rna.tf32.f32 %0, %1;" : "=r"(r) : "f"(f));
    return r;
}
__device__ __forceinline__ void mma_tf32(float* c,
                                         uint32_t a0, uint32_t a1, uint32_t a2, uint32_t a3,
                                         uint32_t b0, uint32_t b1) {
    asm volatile(
        "mma.sync.aligned.m16n8k8.row.col.f32.tf32.tf32.f32 "
        "{%0,%1,%2,%3}, {%4,%5,%6,%7}, {%8,%9}, {%0,%1,%2,%3};"
        : "+f"(c[0]), "+f"(c[1]), "+f"(c[2]), "+f"(c[3])
        : "r"(a0), "r"(a1), "r"(a2), "r"(a3), "r"(b0), "r"(b1));
}

// ---------------- setup: pre-convert conv2 weights ----------------
__global__ void pack_w2_kernel(const float* __restrict__ w2) {
    int i = blockIdx.x * blockDim.x + threadIdx.x;
    if (i >= 160 * 72) return;
    int r = i / 72, nn = i - r * 72;
    uint32_t v = (nn < 64) ? f2tf32(w2[nn * 160 + r]) : 0u;
    ((uint32_t*)g_w2t)[r * 72 + nn] = v;
}

// ---------------- Stage A: conv (4 nodes/block) + fused gat_pre1 ----------
#define H1W   264
#define W2P   72
#define S_H1_OFF  0
#define S_W2_OFF  (32 * H1W)                  // 8448
#define S_IN_OFF  (S_W2_OFF + 160 * W2P)      // 19968
#define S_W1_OFF  (S_IN_OFF + 2 * 208)        // 20384
#define S_RED_OFF (S_W1_OFF + 320)            // 20704
#define S_H0_OFF  (S_RED_OFF + 512)           // 21216
#define S_PT_OFF  (S_H0_OFF + 64)             // 21280
#define CONV_SMEM_FLOATS (S_PT_OFF + 256)     // 21536
#define CONV_SMEM_BYTES  (CONV_SMEM_FLOATS * 4)
#define NODES_PER_BLK 4

__global__ void __launch_bounds__(256, 2)
conv_fused_kernel(const float* __restrict__ x,
                  const float* __restrict__ w1, const float* __restrict__ b1,
                  const float* __restrict__ b2,
                  const float* __restrict__ W1, const float* __restrict__ a1,
                  float* __restrict__ Wh, float* __restrict__ f1, float* __restrict__ f2)
{
    extern __shared__ float sm[];
    float* s_h1  = sm + S_H1_OFF;
    float* s_w2  = sm + S_W2_OFF;
    float* s_in  = sm + S_IN_OFF;
    float* s_w1  = sm + S_W1_OFF;
    float* s_red = sm + S_RED_OFF;
    float* s_h0  = sm + S_H0_OFF;
    float* s_pt  = sm + S_PT_OFF;

    const int tid = threadIdx.x;

    for (int i = tid; i < 320; i += 256) s_w1[i] = w1[i];
    {
        uint4* dst = (uint4*)s_w2;
        for (int i = tid; i < 2880; i += 256) dst[i] = g_w2t[i];
    }
    if (tid < 8) {
        int c = tid >> 2, q = tid & 3;
        s_in[c * 208 + ((q & 1) ? 206 : 0) + (q >> 1)] = 0.f;
    }

    const int warp = tid >> 5;
    const int lane = tid & 31;
    const int g    = lane >> 2;
    const int t4   = lane & 3;

    for (int half = 0; half < NODES_PER_BLK; half++) {
        const int bn = blockIdx.x * NODES_PER_BLK + half;
        const int b  = bn >> 9;
        const int n  = bn & 511;

        const float* xb = x + (size_t)b * SEQ * (NNODES * 2) + 2 * n;
        for (int i = tid; i < 2 * SEQ; i += 256) {
            int s = i >> 1, c = i & 1;
            s_in[c * 208 + 2 + s] = xb[(size_t)s * (NNODES * 2) + c];
        }
        __syncthreads();

        // conv1 + relu -> tf32 h1 (sliding window)
        {
            const int ic = tid >> 3;
            const int j  = tid & 7;
            const int s0 = 25 * j;
            const float b1i = b1[ic];
            const float* w  = s_w1 + ic * 10;
            uint32_t* h1u = (uint32_t*)(s_h1 + ic * H1W);

            float a0[29], a1v[29];
            const float* i0 = s_in + s0;
            const float* i1 = s_in + 208 + s0;
#pragma unroll
            for (int q = 0; q < 29; q++) { a0[q] = i0[q]; a1v[q] = i1[q]; }

#pragma unroll
            for (int q = 0; q < 25; q++) {
                float acc = b1i;
#pragma unroll
                for (int k = 0; k < 5; k++)
                    acc = fmaf(w[k], a0[q + k], fmaf(w[5 + k], a1v[q + k], acc));
                h1u[2 + s0 + q] = f2tf32(fmaxf(acc, 0.f));
            }
            if (j == 0) { h1u[0] = 0u; h1u[1] = 0u; }
            if (j == 7) {
#pragma unroll
                for (int q = 0; q < 10; q++) h1u[202 + q] = 0u;
            }
        }
        __syncthreads();

        // -------- tensor-core GEMM --------
        const uint32_t* h1u = (const uint32_t*)s_h1;
        const uint32_t* w2u = (const uint32_t*)s_w2;

        float c[2][8][4];
#pragma unroll
        for (int mt = 0; mt < 2; mt++)
#pragma unroll
            for (int nt = 0; nt < 8; nt++)
#pragma unroll
                for (int q = 0; q < 4; q++) c[mt][nt][q] = 0.f;

        for (int kc = 0; kc < 20; kc++) {
            const int r0 = kc * 8 + t4;
            const int r1 = r0 + 4;
            const int ic0 = r0 / 5, k0 = r0 - ic0 * 5;
            const int ic1 = r1 / 5, k1 = r1 - ic1 * 5;

            uint32_t bb0[8], bb1[8];
#pragma unroll
            for (int nt = 0; nt < 8; nt++) {
                bb0[nt] = w2u[r0 * W2P + nt * 8 + g];
                bb1[nt] = w2u[r1 * W2P + nt * 8 + g];
            }

            const int ao0 = ic0 * H1W + k0;
            const int ao1 = ic1 * H1W + k1;
#pragma unroll
            for (int mt = 0; mt < 2; mt++) {
                const int tile = warp + 8 * mt;
                if (tile >= 13) continue;
                const int sb = tile * 16 + g;
                uint32_t a0 = h1u[ao0 + sb];
                uint32_t a1 = h1u[ao0 + sb + 8];
                uint32_t a2 = h1u[ao1 + sb];
                uint32_t a3 = h1u[ao1 + sb + 8];
#pragma unroll
                for (int nt = 0; nt < 8; nt++)
                    mma_tf32(c[mt][nt], a0, a1, a2, a3, bb0[nt], bb1[nt]);
            }
        }

        // -------- epilogue: bias + relu + masked sum --------
#pragma unroll
        for (int nt = 0; nt < 8; nt++) {
            const int n0 = nt * 8 + 2 * t4;
            const float bias0 = b2[n0], bias1 = b2[n0 + 1];
            float s0 = 0.f, s1 = 0.f;
#pragma unroll
            for (int mt = 0; mt < 2; mt++) {
                const int tile = warp + 8 * mt;
                if (tile >= 13) continue;
                const int rA = tile * 16 + g;
                const int rB = rA + 8;
                if (rA < 200) {
                    s0 += fmaxf(c[mt][nt][0] + bias0, 0.f);
                    s1 += fmaxf(c[mt][nt][1] + bias1, 0.f);
                }
                if (rB < 200) {
                    s0 += fmaxf(c[mt][nt][2] + bias0, 0.f);
                    s1 += fmaxf(c[mt][nt][3] + bias1, 0.f);
                }
            }
#pragma unroll
            for (int off = 16; off >= 4; off >>= 1) {
                s0 += __shfl_down_sync(0xffffffffu, s0, off);
                s1 += __shfl_down_sync(0xffffffffu, s1, off);
            }
            if (lane < 4) {
                s_red[warp * 64 + nt * 8 + 2 * lane]     = s0;
                s_red[warp * 64 + nt * 8 + 2 * lane + 1] = s1;
            }
        }
        __syncthreads();

        if (tid < 64) {
            float t = 0.f;
#pragma unroll
            for (int w = 0; w < 8; w++) t += s_red[w * 64 + tid];
            s_h0[tid] = t * (1.f / 200.f);
        }
        __syncthreads();

        // -------- fused gat_pre1 --------
        {
            const int kq = tid >> 6;
            const int d  = tid & 63;
            float acc = 0.f;
#pragma unroll
            for (int i = 0; i < 16; i++) {
                int k = kq * 16 + i;
                acc = fmaf(s_h0[k], __ldg(W1 + k * 64 + d), acc);
            }
            s_pt[kq * 64 + d] = acc;
        }
        __syncthreads();

        if (tid < 64) {
            float wh = s_pt[tid] + s_pt[64 + tid] + s_pt[128 + tid] + s_pt[192 + tid];
            Wh[(size_t)bn * 64 + tid] = wh;
            float v1 = wh * __ldg(a1 + tid);
            float v2 = wh * __ldg(a1 + 64 + tid);
#pragma unroll
            for (int o = 16; o; o >>= 1) {
                v1 += __shfl_down_sync(0xffffffffu, v1, o);
                v2 += __shfl_down_sync(0xffffffffu, v2, o);
            }
            if ((tid & 31) == 0) {
                s_pt[(tid >> 5) * 2]     = v1;
                s_pt[(tid >> 5) * 2 + 1] = v2;
            }
        }
        __syncthreads();
        if (tid == 0) {
            f1[bn] = s_pt[0] + s_pt[2];
            f2[bn] = s_pt[1] + s_pt[3];
        }
        __syncthreads();
    }
}

// ---------------- attention smem layout (dynamic, shared by att1/att2) ----
// sp    [16][512]  : 0      .. 8192
// sWh   [64][66]   : 8192   .. 12416   (float2-friendly padding)
// s_f2  [512]      : 12416  .. 12928
// s_hl  [16][64]   : 12928  .. 13952   (att1 only)
// ssum  [16]       : 13952  .. 13968
#define A_SP   0
#define A_SWH  8192
#define A_F2   12416
#define A_HL   12928
#define A_SUM  13952
#define ATT_SMEM_FLOATS 13968
#define ATT_SMEM_BYTES  (ATT_SMEM_FLOATS * 4)

// phase A: 8 warps x 2 rows; int4 adj + smem f2 + __expf
__device__ __forceinline__ void att_softmax_phase(
    float* sp, float* s_f2, float* ssum,
    const float* __restrict__ f1, const float* __restrict__ f2,
    const int* __restrict__ adj, int b, int i0, int tid)
{
    const int w  = tid >> 5;
    const int ln = tid & 31;

    for (int i = tid; i < 512; i += 256) s_f2[i] = f2[b * NNODES + i];
    __syncthreads();

#pragma unroll
    for (int rr = 0; rr < 2; rr++) {
        const int r = w * 2 + rr;
        const int i = i0 + r;
        const float f1i = f1[b * NNODES + i];
        const int4* adj4 = (const int4*)(adj + (size_t)i * NNODES);
        const float4* f2q = (const float4*)s_f2;

        float ev[16];
        float lmax = -3.4e38f;
#pragma unroll
        for (int t = 0; t < 4; t++) {
            int q = ln + 32 * t;
            int4 am = adj4[q];
            float4 fv = f2q[q];
            float e0 = f1i + fv.x; e0 = (e0 > 0.f) ? e0 : ALPHA * e0; e0 = (am.x > 0) ? e0 : NEGBIG;
            float e1 = f1i + fv.y; e1 = (e1 > 0.f) ? e1 : ALPHA * e1; e1 = (am.y > 0) ? e1 : NEGBIG;
            float e2 = f1i + fv.z; e2 = (e2 > 0.f) ? e2 : ALPHA * e2; e2 = (am.z > 0) ? e2 : NEGBIG;
            float e3 = f1i + fv.w; e3 = (e3 > 0.f) ? e3 : ALPHA * e3; e3 = (am.w > 0) ? e3 : NEGBIG;
            ev[4 * t]     = e0; ev[4 * t + 1] = e1;
            ev[4 * t + 2] = e2; ev[4 * t + 3] = e3;
            lmax = fmaxf(lmax, fmaxf(fmaxf(e0, e1), fmaxf(e2, e3)));
        }
#pragma unroll
        for (int o = 16; o; o >>= 1)
            lmax = fmaxf(lmax, __shfl_xor_sync(0xffffffffu, lmax, o));

        float lsum = 0.f;
        float4* spr = (float4*)(sp + r * 512);
#pragma unroll
        for (int t = 0; t < 4; t++) {
            int q = ln + 32 * t;
            float4 pv;
            pv.x = __expf(ev[4 * t]     - lmax);
            pv.y = __expf(ev[4 * t + 1] - lmax);
            pv.z = __expf(ev[4 * t + 2] - lmax);
            pv.w = __expf(ev[4 * t + 3] - lmax);
            spr[q] = pv;
            lsum += pv.x + pv.y + pv.z + pv.w;
        }
#pragma unroll
        for (int o = 16; o; o >>= 1)
            lsum += __shfl_xor_sync(0xffffffffu, lsum, o);
        if (ln == 0) ssum[r] = lsum;
    }
    __syncthreads();
}

// phase B: 16 rows x 64 d, 4 outputs/thread (2 rows x float2 d)
__device__ __forceinline__ void att_agg_phase(
    const float* sp, float* sWh, const float* __restrict__ Whb,
    int p, int dq, float& a00, float& a01, float& a10, float& a11, int tid)
{
    a00 = a01 = a10 = a11 = 0.f;
    for (int jt = 0; jt < 8; jt++) {
#pragma unroll
        for (int t = 0; t < 16; t++) {
            int idx = tid + t * 256;
            int j = idx >> 6, dd = idx & 63;
            sWh[j * 66 + dd] = Whb[(size_t)(jt * 64 + j) * 64 + dd];
        }
        __syncthreads();
        const float* p0 = sp + (2 * p) * 512 + jt * 64;
        const float* p1 = p0 + 512;
#pragma unroll 8
        for (int j = 0; j < 64; j++) {
            float2 wv = ((const float2*)(sWh + j * 66))[dq];
            float pa = p0[j], pb = p1[j];
            a00 = fmaf(pa, wv.x, a00); a01 = fmaf(pa, wv.y, a01);
            a10 = fmaf(pb, wv.x, a10); a11 = fmaf(pb, wv.y, a11);
        }
        __syncthreads();
    }
}

// ---------------- Stage B: attention layer1 + fused gat_pre2 ----------
__global__ void __launch_bounds__(256)
gat_att1_kernel(const float* __restrict__ Wh, const float* __restrict__ f1,
                const float* __restrict__ f2, const int* __restrict__ adj,
                const float* __restrict__ W2, const float* __restrict__ a2,
                float* __restrict__ Wh2, float* __restrict__ f1o, float* __restrict__ f2o)
{
    extern __shared__ float dsm[];
    float* sp   = dsm + A_SP;
    float* sWh  = dsm + A_SWH;
    float* s_f2 = dsm + A_F2;
    float* s_hl = dsm + A_HL;
    float* ssum = dsm + A_SUM;

    const int blk = blockIdx.x;
    const int b   = blk >> 5;
    const int i0  = (blk & 31) * 16;
    const int tid = threadIdx.x;
    const int p   = tid >> 5;
    const int dq  = tid & 31;

    att_softmax_phase(sp, s_f2, ssum, f1, f2, adj, b, i0, tid);

    float a00, a01, a10, a11;
    att_agg_phase(sp, sWh, Wh + (size_t)b * NNODES * HID, p, dq, a00, a01, a10, a11, tid);

    // h1 rows (relu) -> smem (warp p owns rows 2p, 2p+1 fully)
    {
        float inv0 = 1.f / ssum[2 * p];
        float inv1 = 1.f / ssum[2 * p + 1];
        ((float2*)(s_hl + (2 * p) * 64))[dq] =
            make_float2(fmaxf(a00 * inv0, 0.f), fmaxf(a01 * inv0, 0.f));
        ((float2*)(s_hl + (2 * p + 1) * 64))[dq] =
            make_float2(fmaxf(a10 * inv1, 0.f), fmaxf(a11 * inv1, 0.f));
    }
    // load W2 into sWh
#pragma unroll
    for (int t = 0; t < 16; t++) {
        int idx = tid + t * 256;
        sWh[(idx >> 6) * 66 + (idx & 63)] = W2[idx];
    }
    __syncthreads();

    // fused gat_pre2
    {
        float w00 = 0.f, w01 = 0.f, w10 = 0.f, w11 = 0.f;
        const float* h0r = s_hl + (2 * p) * 64;
        const float* h1r = h0r + 64;
#pragma unroll 8
        for (int k = 0; k < 64; k++) {
            float2 wv = ((const float2*)(sWh + k * 66))[dq];
            float ha = h0r[k], hb = h1r[k];
            w00 = fmaf(ha, wv.x, w00); w01 = fmaf(ha, wv.y, w01);
            w10 = fmaf(hb, wv.x, w10); w11 = fmaf(hb, wv.y, w11);
        }
        const int row0 = b * NNODES + i0 + 2 * p;
        ((float2*)(Wh2 + (size_t)row0 * 64))[dq]       = make_float2(w00, w01);
        ((float2*)(Wh2 + (size_t)(row0 + 1) * 64))[dq] = make_float2(w10, w11);

        const int d0 = 2 * dq;
        const float ax = __ldg(a2 + d0),      ay = __ldg(a2 + d0 + 1);
        const float bx = __ldg(a2 + 64 + d0), by = __ldg(a2 + 64 + d0 + 1);
        float u0 = w00 * ax + w01 * ay;
        float v0 = w00 * bx + w01 * by;
        float u1 = w10 * ax + w11 * ay;
        float v1 = w10 * bx + w11 * by;
#pragma unroll
        for (int o = 16; o; o >>= 1) {
            u0 += __shfl_down_sync(0xffffffffu, u0, o);
            v0 += __shfl_down_sync(0xffffffffu, v0, o);
            u1 += __shfl_down_sync(0xffffffffu, u1, o);
            v1 += __shfl_down_sync(0xffffffffu, v1, o);
        }
        if (dq == 0) {
            f1o[row0]     = u0;
            f2o[row0]     = v0;
            f1o[row0 + 1] = u1;
            f2o[row0 + 1] = v1;
        }
    }
}

// ---------------- Stage C: attention layer2 ----------
__global__ void __launch_bounds__(256)
gat_att2_kernel(const float* __restrict__ Wh, const float* __restrict__ f1,
                const float* __restrict__ f2, const int* __restrict__ adj,
                float* __restrict__ out)
{
    extern __shared__ float dsm[];
    float* sp   = dsm + A_SP;
    float* sWh  = dsm + A_SWH;
    float* s_f2 = dsm + A_F2;
    float* ssum = dsm + A_SUM;

    const int blk = blockIdx.x;
    const int b   = blk >> 5;
    const int i0  = (blk & 31) * 16;
    const int tid = threadIdx.x;
    const int p   = tid >> 5;
    const int dq  = tid & 31;

    att_softmax_phase(sp, s_f2, ssum, f1, f2, adj, b, i0, tid);

    float a00, a01, a10, a11;
    att_agg_phase(sp, sWh, Wh + (size_t)b * NNODES * HID, p, dq, a00, a01, a10, a11, tid);

    const float inv0 = 1.f / ssum[2 * p];
    const float inv1 = 1.f / ssum[2 * p + 1];
    const int row0 = b * NNODES + i0 + 2 * p;
    ((float2*)(out + (size_t)row0 * 64))[dq]       = make_float2(a00 * inv0, a01 * inv0);
    ((float2*)(out + (size_t)(row0 + 1) * 64))[dq] = make_float2(a10 * inv1, a11 * inv1);
}

// ---------------- Stage D: edge gather + MLP + sigmoid ----------------
__global__ void __launch_bounds__(64)
edge_mlp_kernel(const float* __restrict__ h, const int* __restrict__ eidx,
                const float* __restrict__ fc1w, const float* __restrict__ fc1b,
                const float* __restrict__ fc2w, const float* __restrict__ fc2b,
                float* __restrict__ out)
{
    __shared__ float she[128];
    __shared__ float sr[2];

    const int e   = blockIdx.x;
    const int b   = blockIdx.y;
    const int tid = threadIdx.x;

    const int i1 = eidx[2 * e];
    const int i2 = eidx[2 * e + 1];
    she[tid]      = h[((size_t)b * NNODES + i1) * HID + tid];
    she[64 + tid] = h[((size_t)b * NNODES + i2) * HID + tid];
    __syncthreads();

    float acc = fc1b[tid];
#pragma unroll 8
    for (int k = 0; k < 128; k++)
        acc = fmaf(she[k], fc1w[(size_t)k * 64 + tid], acc);
    acc = fmaxf(acc, 0.f);

    float v = acc * fc2w[tid];
#pragma unroll
    for (int o = 16; o; o >>= 1)
        v += __shfl_down_sync(0xffffffffu, v, o);
    if ((tid & 31) == 0) sr[tid >> 5] = v;
    __syncthreads();
    if (tid == 0) {
        float z = sr[0] + sr[1] + fc2b[0];
        out[(size_t)b * NEDGES + e] = 1.f / (1.f + expf(-z));
    }
}

// ---------------- launch ----------------
extern "C" void kernel_launch(void* const* d_in, const int* in_sizes, int n_in,
                              void* d_out, int out_size)
{
    const float* x    = (const float*)d_in[0];
    const int*   adj  = (const int*)  d_in[1];
    const int*   eidx = (const int*)  d_in[2];
    const float* w1   = (const float*)d_in[3];
    const float* b1   = (const float*)d_in[4];
    const float* w2   = (const float*)d_in[5];
    const float* b2   = (const float*)d_in[6];
    const float* W1   = (const float*)d_in[7];
    const float* a1   = (const float*)d_in[8];
    const float* W2   = (const float*)d_in[9];
    const float* a2   = (const float*)d_in[10];
    const float* fc1w = (const float*)d_in[11];
    const float* fc1b = (const float*)d_in[12];
    const float* fc2w = (const float*)d_in[13];
    const float* fc2b = (const float*)d_in[14];
    float* out = (float*)d_out;

    float *Wh1, *Wh2, *h2, *f1a, *f2a, *f1b, *f2b;
    cudaGetSymbolAddress((void**)&Wh1, g_Wh1);
    cudaGetSymbolAddress((void**)&Wh2, g_Wh2);
    cudaGetSymbolAddress((void**)&h2,  g_h2);
    cudaGetSymbolAddress((void**)&f1a, g_f1a);
    cudaGetSymbolAddress((void**)&f2a, g_f2a);
    cudaGetSymbolAddress((void**)&f1b, g_f1b);
    cudaGetSymbolAddress((void**)&f2b, g_f2b);

    cudaFuncSetAttribute(conv_fused_kernel,
                         cudaFuncAttributeMaxDynamicSharedMemorySize,
                         CONV_SMEM_BYTES);
    cudaFuncSetAttribute(gat_att1_kernel,
                         cudaFuncAttributeMaxDynamicSharedMemorySize,
                         ATT_SMEM_BYTES);
    cudaFuncSetAttribute(gat_att2_kernel,
                         cudaFuncAttributeMaxDynamicSharedMemorySize,
                         ATT_SMEM_BYTES);

    pack_w2_kernel<<<(160 * 72 + 255) / 256, 256>>>(w2);

    conv_fused_kernel<<<(BATCH * NNODES) / NODES_PER_BLK, 256, CONV_SMEM_BYTES>>>(
        x, w1, b1, b2, W1, a1, Wh1, f1a, f2a);

    gat_att1_kernel<<<(BATCH * NNODES) / 16, 256, ATT_SMEM_BYTES>>>(
        Wh1, f1a, f2a, adj, W2, a2, Wh2, f1b, f2b);

    gat_att2_kernel<<<(BATCH * NNODES) / 16, 256, ATT_SMEM_BYTES>>>(
        Wh2, f1b, f2b, adj, h2);

    dim3 eg(NEDGES, BATCH);
    edge_mlp_kernel<<<eg, 64>>>(h2, eidx, fc1w, fc1b, fc2w, fc2b, out);
}